// round 6
// baseline (speedup 1.0000x reference)
#include <cuda_runtime.h>
#include <cuda_fp16.h>
#include <math.h>

#define NMAX 50000
#define EMAX 800000
#define F 64
#define NH 4
#define NPB 32          // nodes per fused block

// ---------------- scratch (device globals; referenced ONLY from device code) ----------------
__device__ float   g_xln[NMAX * F];           // Tx0 (layernormed x)
__device__ float   g_tx1[NMAX * F];           // Tx1 = L_hat @ Tx0
__device__ __half2 g_xh16[(size_t)NMAX * 128];// projected features, [node][head][feat/2]
__device__ float   g_asrc[NMAX * NH];
__device__ float   g_adst[NMAX * NH];
__device__ float   g_deg[NMAX];
__device__ float   g_dinv[NMAX];
__device__ int     g_cnt[NMAX];               // in-degree counts (by dst)
__device__ int     g_loc[NMAX];               // per-block local exclusive prefix
__device__ int     g_bsum[256];               // per-block sums -> exclusive offsets
__device__ int     g_rowptr[NMAX + 1];        // CSR row pointers (by dst)
__device__ int     g_cursor[NMAX];            // fill cursors
__device__ int2    g_cse[EMAX];               // CSR: (src, weight-as-int) per slot

__device__ __forceinline__ float leaky(float x, float s) {
    return x >= 0.f ? x : s * x;
}

// ---------------- kernels ----------------
__global__ void k_init(int n) {
    int i = blockIdx.x * blockDim.x + threadIdx.x;
    if (i < n) { g_deg[i] = 0.f; g_cnt[i] = 0; }
}

// one warp per node; lane handles c and c+32
__global__ void k_ln(const float* __restrict__ x, const float* __restrict__ gamma,
                     const float* __restrict__ beta, int n) {
    int warp = (blockIdx.x * blockDim.x + threadIdx.x) >> 5;
    int lane = threadIdx.x & 31;
    if (warp >= n) return;
    const float* xr = x + (size_t)warp * F;
    float a = xr[lane], b = xr[lane + 32];
    float s = a + b, sq = a * a + b * b;
    #pragma unroll
    for (int o = 16; o; o >>= 1) {
        s  += __shfl_xor_sync(0xffffffffu, s,  o);
        sq += __shfl_xor_sync(0xffffffffu, sq, o);
    }
    float mu  = s * (1.f / 64.f);
    float var = sq * (1.f / 64.f) - mu * mu;
    float r = rsqrtf(var + 1e-5f);
    g_xln[warp * F + lane]      = (a - mu) * r * gamma[lane]      + beta[lane];
    g_xln[warp * F + lane + 32] = (b - mu) * r * gamma[lane + 32] + beta[lane + 32];
}

// weighted out-degree by src + in-degree count by dst
__global__ void k_degcnt(const int* __restrict__ src, const int* __restrict__ dst,
                         const float* __restrict__ ea, int e) {
    int i = blockIdx.x * blockDim.x + threadIdx.x;
    if (i >= e) return;
    atomicAdd(&g_deg[src[i]], ea[i]);
    atomicAdd(&g_cnt[dst[i]], 1);
}

// ---- 3-phase parallel exclusive scan of g_cnt ----
__global__ void k_scan1(int n) {
    __shared__ int sm[256];
    int t = threadIdx.x;
    int i = blockIdx.x * 256 + t;
    int v = (i < n) ? g_cnt[i] : 0;
    sm[t] = v;
    __syncthreads();
    for (int o = 1; o < 256; o <<= 1) {
        int u = (t >= o) ? sm[t - o] : 0;
        __syncthreads();
        sm[t] += u;
        __syncthreads();
    }
    if (i < n) g_loc[i] = sm[t] - v;
    if (t == 255) g_bsum[blockIdx.x] = sm[255];
}

__global__ void k_scan2(int nb) {
    __shared__ int sm[256];
    int t = threadIdx.x;
    int v = (t < nb) ? g_bsum[t] : 0;
    sm[t] = v;
    __syncthreads();
    for (int o = 1; o < 256; o <<= 1) {
        int u = (t >= o) ? sm[t - o] : 0;
        __syncthreads();
        sm[t] += u;
        __syncthreads();
    }
    if (t < nb) g_bsum[t] = sm[t] - v;
}

__global__ void k_scan3(int n, int e) {
    int i = blockIdx.x * blockDim.x + threadIdx.x;
    if (i < n) {
        int r = g_bsum[i >> 8] + g_loc[i];
        g_rowptr[i] = r;
        g_cursor[i] = r;
        float d = g_deg[i];
        g_dinv[i] = d > 0.f ? rsqrtf(d) : 0.f;
    }
    if (i == 0) g_rowptr[n] = e;
}

// scatter edges into CSR slots; compute Laplacian weight inline
__global__ void k_fill(const int* __restrict__ src, const int* __restrict__ dst,
                       const float* __restrict__ ea, int e) {
    int i = blockIdx.x * blockDim.x + threadIdx.x;
    if (i >= e) return;
    int s = src[i], d = dst[i];
    int pos = atomicAdd(&g_cursor[d], 1);
    float w = -(g_dinv[s] * ea[i] * g_dinv[d]);
    g_cse[pos] = make_int2(s, __float_as_int(w));
}

// gather propagation xln -> tx1; warp per node; float2 per lane; 4-edge ILP
__global__ void k_prop(int n) {
    int node = (blockIdx.x * blockDim.x + threadIdx.x) >> 5;
    int lane = threadIdx.x & 31;
    if (node >= n) return;
    const float2* in2 = (const float2*)g_xln;
    int beg = g_rowptr[node], end = g_rowptr[node + 1];
    float2 a0 = {0.f, 0.f}, a1 = {0.f, 0.f}, a2 = {0.f, 0.f}, a3 = {0.f, 0.f};
    int j = beg;
    for (; j + 4 <= end; j += 4) {
        int2 e0 = __ldg(&g_cse[j]),     e1 = __ldg(&g_cse[j + 1]);
        int2 e2 = __ldg(&g_cse[j + 2]), e3 = __ldg(&g_cse[j + 3]);
        float2 r0 = in2[(size_t)e0.x * 32 + lane];
        float2 r1 = in2[(size_t)e1.x * 32 + lane];
        float2 r2 = in2[(size_t)e2.x * 32 + lane];
        float2 r3 = in2[(size_t)e3.x * 32 + lane];
        float w0 = __int_as_float(e0.y), w1 = __int_as_float(e1.y);
        float w2 = __int_as_float(e2.y), w3 = __int_as_float(e3.y);
        a0.x = fmaf(w0, r0.x, a0.x); a0.y = fmaf(w0, r0.y, a0.y);
        a1.x = fmaf(w1, r1.x, a1.x); a1.y = fmaf(w1, r1.y, a1.y);
        a2.x = fmaf(w2, r2.x, a2.x); a2.y = fmaf(w2, r2.y, a2.y);
        a3.x = fmaf(w3, r3.x, a3.x); a3.y = fmaf(w3, r3.y, a3.y);
    }
    for (; j < end; j++) {
        int2 e0 = __ldg(&g_cse[j]);
        float w0 = __int_as_float(e0.y);
        float2 r0 = in2[(size_t)e0.x * 32 + lane];
        a0.x = fmaf(w0, r0.x, a0.x); a0.y = fmaf(w0, r0.y, a0.y);
    }
    float2 s;
    s.x = (a0.x + a1.x) + (a2.x + a3.x);
    s.y = (a0.y + a1.y) + (a2.y + a3.y);
    ((float2*)g_tx1)[(size_t)node * 32 + lane] = s;
}

// fused: tx2-gather + Cheb-combine + GAT projection + attention dots.
// 32 nodes per 256-thread block.
__global__ void __launch_bounds__(256) k_fused(
        const float* __restrict__ cw, const float* __restrict__ cb,
        const float* __restrict__ gw, const float* __restrict__ as,
        const float* __restrict__ ad, int n) {
    __shared__ float s_in[NPB][3][F];     // 24KB
    __shared__ float s_h[NPB][F];         // 8KB
    __shared__ float s_red[2][8][NPB];    // 2KB
    int t = threadIdx.x;
    int base = blockIdx.x * NPB;
    int lane = t & 31, w = t >> 5;

    // own rows of Tx0 / Tx1
    for (int i = t; i < NPB * F; i += 256) {
        int m = i >> 6, c = i & 63;
        int node = base + m;
        if (node < n) {
            s_in[m][0][c] = g_xln[node * F + c];
            s_in[m][1][c] = g_tx1[node * F + c];
        }
    }
    // gather Tx2 = L_hat @ Tx1 (warp w handles nodes w, w+8, w+16, w+24)
    const float2* in2 = (const float2*)g_tx1;
    #pragma unroll
    for (int q = 0; q < 4; q++) {
        int m = w + 8 * q;
        int node = base + m;
        if (node < n) {
            int beg = g_rowptr[node], end = g_rowptr[node + 1];
            float2 a0 = {0.f, 0.f}, a1 = {0.f, 0.f};
            int j = beg;
            for (; j + 2 <= end; j += 2) {
                int2 e0 = __ldg(&g_cse[j]), e1 = __ldg(&g_cse[j + 1]);
                float2 r0 = in2[(size_t)e0.x * 32 + lane];
                float2 r1 = in2[(size_t)e1.x * 32 + lane];
                float w0 = __int_as_float(e0.y), w1 = __int_as_float(e1.y);
                a0.x = fmaf(w0, r0.x, a0.x); a0.y = fmaf(w0, r0.y, a0.y);
                a1.x = fmaf(w1, r1.x, a1.x); a1.y = fmaf(w1, r1.y, a1.y);
            }
            if (j < end) {
                int2 e0 = __ldg(&g_cse[j]);
                float w0 = __int_as_float(e0.y);
                float2 r0 = in2[(size_t)e0.x * 32 + lane];
                a0.x = fmaf(w0, r0.x, a0.x); a0.y = fmaf(w0, r0.y, a0.y);
            }
            ((float2*)s_in[m][2])[lane] = make_float2(a0.x + a1.x, a0.y + a1.y);
        }
    }
    __syncthreads();

    // Cheb: thread handles output column o for nodes m = g + 4q, q=0..7
    int o = t & 63, g = t >> 6;
    float accc[8] = {0.f, 0.f, 0.f, 0.f, 0.f, 0.f, 0.f, 0.f};
    #pragma unroll 4
    for (int c = 0; c < F; c++) {
        float w0 = cw[c * F + o];
        float w1 = cw[F * F + c * F + o];
        float w2 = cw[2 * F * F + c * F + o];
        #pragma unroll
        for (int q = 0; q < 8; q++) {
            int m = g + 4 * q;
            float a0 = s_in[m][0][c], a1 = s_in[m][1][c];
            float a2 = 2.f * s_in[m][2][c] - a0;
            accc[q] = fmaf(a0, w0, fmaf(a1, w1, fmaf(a2, w2, accc[q])));
        }
    }
    float bias = cb[o];
    #pragma unroll
    for (int q = 0; q < 8; q++)
        s_h[g + 4 * q][o] = leaky(accc[q] + bias, 0.01f);
    __syncthreads();

    // xw: thread computes output column j = t (head j>>6, feature j&63) for all 32 nodes
    int j = t;
    float acc[NPB];
    #pragma unroll
    for (int m = 0; m < NPB; m++) acc[m] = 0.f;
    #pragma unroll 2
    for (int c4 = 0; c4 < F / 4; c4++) {
        float w0 = gw[(c4 * 4 + 0) * 256 + j];
        float w1 = gw[(c4 * 4 + 1) * 256 + j];
        float w2 = gw[(c4 * 4 + 2) * 256 + j];
        float w3 = gw[(c4 * 4 + 3) * 256 + j];
        #pragma unroll
        for (int m = 0; m < NPB; m++) {
            float4 hv = *reinterpret_cast<const float4*>(&s_h[m][c4 * 4]);
            acc[m] = fmaf(hv.x, w0, fmaf(hv.y, w1, fmaf(hv.z, w2, fmaf(hv.w, w3, acc[m]))));
        }
    }

    // write xh as half2 (features 2c', 2c'+1 packed)
    int c = t & 63, h = t >> 6;
    #pragma unroll
    for (int m = 0; m < NPB; m++) {
        float other = __shfl_xor_sync(0xffffffffu, acc[m], 1);
        int node = base + m;
        if (!(c & 1) && node < n) {
            __half2 hv = __floats2half2_rn(acc[m], other);
            g_xh16[(size_t)node * 128 + h * 32 + (c >> 1)] = hv;
        }
    }

    // attention dots
    float asj = as[j], adj = ad[j];
    #pragma unroll
    for (int m = 0; m < NPB; m++) {
        float sv = acc[m] * asj, dv = acc[m] * adj;
        #pragma unroll
        for (int off = 16; off; off >>= 1) {
            sv += __shfl_xor_sync(0xffffffffu, sv, off);
            dv += __shfl_xor_sync(0xffffffffu, dv, off);
        }
        if (lane == 0) { s_red[0][w][m] = sv; s_red[1][w][m] = dv; }
    }
    __syncthreads();
    if (t < 128) {
        int hh = t >> 5, m = t & 31;
        int node = base + m;
        if (node < n) {
            g_asrc[node * NH + hh] = s_red[0][2 * hh][m] + s_red[0][2 * hh + 1][m];
            g_adst[node * NH + hh] = s_red[1][2 * hh][m] + s_red[1][2 * hh + 1][m];
        }
    }
}

// fused GAT, single edge sweep. warp per node.
// lane owns head (lane>>3), features (lane&7)*8..+7 -> one LDG.128 per edge per lane.
__global__ void k_gat(const float* __restrict__ gb, float* __restrict__ out, int n) {
    __shared__ float4 s_ex[8][32];
    __shared__ int    s_s[8][32];
    int wid = threadIdx.x >> 5;
    int node = (blockIdx.x * blockDim.x + threadIdx.x) >> 5;
    int lane = threadIdx.x & 31;
    if (node >= n) return;
    int beg = g_rowptr[node], end = g_rowptr[node + 1];
    int myh = lane >> 3;

    const float4* pa = reinterpret_cast<const float4*>(g_asrc);
    const float4* pd = reinterpret_cast<const float4*>(g_adst);
    float4 adv = pd[node];
    float4 asn = pa[node];
    float selfex[NH];
    selfex[0] = __expf(leaky(asn.x + adv.x, 0.2f));
    selfex[1] = __expf(leaky(asn.y + adv.y, 0.2f));
    selfex[2] = __expf(leaky(asn.z + adv.z, 0.2f));
    selfex[3] = __expf(leaky(asn.w + adv.w, 0.2f));

    const uint4* xh = reinterpret_cast<const uint4*>(g_xh16);
    float a[8];
    {   // self term
        uint4 v = __ldg(&xh[(size_t)node * 32 + lane]);
        const __half2* h2 = reinterpret_cast<const __half2*>(&v);
        float alpha = selfex[myh];
        #pragma unroll
        for (int i = 0; i < 4; i++) {
            float2 f = __half22float2(h2[i]);
            a[2 * i]     = alpha * f.x;
            a[2 * i + 1] = alpha * f.y;
        }
    }
    float den[NH] = {0.f, 0.f, 0.f, 0.f};

    for (int j0 = beg; j0 < end; j0 += 32) {
        int cnt = min(32, end - j0);
        float4 ex = make_float4(0.f, 0.f, 0.f, 0.f);
        int s = 0;
        if (lane < cnt) {
            s = __ldg(&g_cse[j0 + lane]).x;
            float4 av = pa[s];
            ex.x = __expf(leaky(av.x + adv.x, 0.2f));
            ex.y = __expf(leaky(av.y + adv.y, 0.2f));
            ex.z = __expf(leaky(av.z + adv.z, 0.2f));
            ex.w = __expf(leaky(av.w + adv.w, 0.2f));
            den[0] += ex.x; den[1] += ex.y; den[2] += ex.z; den[3] += ex.w;
        }
        s_ex[wid][lane] = ex;
        s_s[wid][lane] = s;
        __syncwarp();
        #pragma unroll 2
        for (int k = 0; k < cnt; k++) {
            int sk = s_s[wid][k];
            float alpha = reinterpret_cast<const float*>(&s_ex[wid][k])[myh];
            uint4 v = __ldg(&xh[(size_t)sk * 32 + lane]);
            const __half2* h2 = reinterpret_cast<const __half2*>(&v);
            #pragma unroll
            for (int i = 0; i < 4; i++) {
                float2 f = __half22float2(h2[i]);
                a[2 * i]     = fmaf(alpha, f.x, a[2 * i]);
                a[2 * i + 1] = fmaf(alpha, f.y, a[2 * i + 1]);
            }
        }
        __syncwarp();
    }

    #pragma unroll
    for (int o = 16; o; o >>= 1)
        #pragma unroll
        for (int h = 0; h < NH; h++)
            den[h] += __shfl_xor_sync(0xffffffffu, den[h], o);
    float iv = 1.f / (den[myh] + selfex[myh] + 1e-16f);

    // normalize by own head's denom, then sum across heads (lanes ^8, ^16)
    #pragma unroll
    for (int i = 0; i < 8; i++) {
        float r = a[i] * iv;
        r += __shfl_xor_sync(0xffffffffu, r, 8);
        r += __shfl_xor_sync(0xffffffffu, r, 16);
        a[i] = r;
    }
    if (lane < 8) {
        float* op = out + (size_t)node * F + lane * 8;
        #pragma unroll
        for (int i = 0; i < 8; i++)
            op[i] = leaky(0.25f * a[i] + gb[lane * 8 + i], 0.01f);
    }
}

// ---------------- launch ----------------
extern "C" void kernel_launch(void* const* d_in, const int* in_sizes, int n_in,
                              void* d_out, int out_size) {
    const float* x      = (const float*)d_in[0];
    const int*   ei     = (const int*)  d_in[1];
    const float* ea     = (const float*)d_in[2];
    const float* lng    = (const float*)d_in[3];
    const float* lnb    = (const float*)d_in[4];
    const float* cw     = (const float*)d_in[5];
    const float* cb     = (const float*)d_in[6];
    const float* gw     = (const float*)d_in[7];
    const float* as     = (const float*)d_in[8];
    const float* ad     = (const float*)d_in[9];
    const float* gb     = (const float*)d_in[10];
    float* out = (float*)d_out;

    const int n = in_sizes[0] / F;        // 50000
    const int e = in_sizes[2];            // 800000
    const int* src = ei;
    const int* dst = ei + e;

    const int TB = 256;
    auto cdiv = [](long long a, long long b) { return (int)((a + b - 1) / b); };
    int nb = cdiv(n, 256);

    k_init  <<<cdiv(n, TB), TB>>>(n);
    k_ln    <<<cdiv((long long)n * 32, TB), TB>>>(x, lng, lnb, n);
    k_degcnt<<<cdiv(e, TB), TB>>>(src, dst, ea, e);
    k_scan1 <<<nb, 256>>>(n);
    k_scan2 <<<1, 256>>>(nb);
    k_scan3 <<<cdiv(n, TB), TB>>>(n, e);
    k_fill  <<<cdiv(e, TB), TB>>>(src, dst, ea, e);
    k_prop  <<<cdiv((long long)n * 32, TB), TB>>>(n);
    k_fused <<<cdiv(n, NPB), 256>>>(cw, cb, gw, as, ad, n);
    k_gat   <<<cdiv((long long)n * 32, TB), TB>>>(gb, out, n);
}

// round 7
// speedup vs baseline: 1.0760x; 1.0760x over previous
#include <cuda_runtime.h>
#include <cuda_fp16.h>
#include <math.h>

#define NMAX 50000
#define EMAX 800000
#define F 64
#define NH 4
#define NPB 16          // nodes per fused block

// ---------------- scratch (device globals; referenced ONLY from device code) ----------------
__device__ float   g_xln[NMAX * F];           // Tx0 (layernormed x)
__device__ float   g_tx1[NMAX * F];           // Tx1 = L_hat @ Tx0
__device__ float   g_tx2[NMAX * F];           // L_hat @ Tx1
__device__ __half2 g_xh16[(size_t)NMAX * 128];// projected features, [node][head][feat/2]
__device__ float   g_asrc[NMAX * NH];
__device__ float   g_adst[NMAX * NH];
__device__ float   g_deg[NMAX];
__device__ float   g_dinv[NMAX];
__device__ int     g_cnt[NMAX];               // in-degree counts (by dst)
__device__ int     g_loc[NMAX];               // per-block local exclusive prefix
__device__ int     g_bsum[256];               // per-block sums -> exclusive offsets
__device__ int     g_rowptr[NMAX + 1];        // CSR row pointers (by dst)
__device__ int     g_cursor[NMAX];            // fill cursors
__device__ int2    g_cse[EMAX];               // CSR: (src, weight-as-int) per slot

__device__ __forceinline__ float leaky(float x, float s) {
    return x >= 0.f ? x : s * x;
}

// ---------------- kernels ----------------
__global__ void k_init(int n) {
    int i = blockIdx.x * blockDim.x + threadIdx.x;
    if (i < n) { g_deg[i] = 0.f; g_cnt[i] = 0; }
}

// one warp per node; lane handles c and c+32
__global__ void k_ln(const float* __restrict__ x, const float* __restrict__ gamma,
                     const float* __restrict__ beta, int n) {
    int warp = (blockIdx.x * blockDim.x + threadIdx.x) >> 5;
    int lane = threadIdx.x & 31;
    if (warp >= n) return;
    const float* xr = x + (size_t)warp * F;
    float a = xr[lane], b = xr[lane + 32];
    float s = a + b, sq = a * a + b * b;
    #pragma unroll
    for (int o = 16; o; o >>= 1) {
        s  += __shfl_xor_sync(0xffffffffu, s,  o);
        sq += __shfl_xor_sync(0xffffffffu, sq, o);
    }
    float mu  = s * (1.f / 64.f);
    float var = sq * (1.f / 64.f) - mu * mu;
    float r = rsqrtf(var + 1e-5f);
    g_xln[warp * F + lane]      = (a - mu) * r * gamma[lane]      + beta[lane];
    g_xln[warp * F + lane + 32] = (b - mu) * r * gamma[lane + 32] + beta[lane + 32];
}

// weighted out-degree by src + in-degree count by dst
__global__ void k_degcnt(const int* __restrict__ src, const int* __restrict__ dst,
                         const float* __restrict__ ea, int e) {
    int i = blockIdx.x * blockDim.x + threadIdx.x;
    if (i >= e) return;
    atomicAdd(&g_deg[src[i]], ea[i]);
    atomicAdd(&g_cnt[dst[i]], 1);
}

// ---- 3-phase parallel exclusive scan of g_cnt ----
__global__ void k_scan1(int n) {
    __shared__ int sm[256];
    int t = threadIdx.x;
    int i = blockIdx.x * 256 + t;
    int v = (i < n) ? g_cnt[i] : 0;
    sm[t] = v;
    __syncthreads();
    for (int o = 1; o < 256; o <<= 1) {
        int u = (t >= o) ? sm[t - o] : 0;
        __syncthreads();
        sm[t] += u;
        __syncthreads();
    }
    if (i < n) g_loc[i] = sm[t] - v;
    if (t == 255) g_bsum[blockIdx.x] = sm[255];
}

__global__ void k_scan2(int nb) {
    __shared__ int sm[256];
    int t = threadIdx.x;
    int v = (t < nb) ? g_bsum[t] : 0;
    sm[t] = v;
    __syncthreads();
    for (int o = 1; o < 256; o <<= 1) {
        int u = (t >= o) ? sm[t - o] : 0;
        __syncthreads();
        sm[t] += u;
        __syncthreads();
    }
    if (t < nb) g_bsum[t] = sm[t] - v;
}

__global__ void k_scan3(int n, int e) {
    int i = blockIdx.x * blockDim.x + threadIdx.x;
    if (i < n) {
        int r = g_bsum[i >> 8] + g_loc[i];
        g_rowptr[i] = r;
        g_cursor[i] = r;
        float d = g_deg[i];
        g_dinv[i] = d > 0.f ? rsqrtf(d) : 0.f;
    }
    if (i == 0) g_rowptr[n] = e;
}

// scatter edges into CSR slots; compute Laplacian weight inline
__global__ void k_fill(const int* __restrict__ src, const int* __restrict__ dst,
                       const float* __restrict__ ea, int e) {
    int i = blockIdx.x * blockDim.x + threadIdx.x;
    if (i >= e) return;
    int s = src[i], d = dst[i];
    int pos = atomicAdd(&g_cursor[d], 1);
    float w = -(g_dinv[s] * ea[i] * g_dinv[d]);
    g_cse[pos] = make_int2(s, __float_as_int(w));
}

// gather propagation; warp per node; float2 per lane; 4-edge ILP
__global__ void k_prop(int n, int phase) {
    int node = (blockIdx.x * blockDim.x + threadIdx.x) >> 5;
    int lane = threadIdx.x & 31;
    if (node >= n) return;
    const float2* in2 = phase ? (const float2*)g_tx1 : (const float2*)g_xln;
    int beg = g_rowptr[node], end = g_rowptr[node + 1];
    float2 a0 = {0.f, 0.f}, a1 = {0.f, 0.f}, a2 = {0.f, 0.f}, a3 = {0.f, 0.f};
    int j = beg;
    for (; j + 4 <= end; j += 4) {
        int2 e0 = __ldg(&g_cse[j]),     e1 = __ldg(&g_cse[j + 1]);
        int2 e2 = __ldg(&g_cse[j + 2]), e3 = __ldg(&g_cse[j + 3]);
        float2 r0 = in2[(size_t)e0.x * 32 + lane];
        float2 r1 = in2[(size_t)e1.x * 32 + lane];
        float2 r2 = in2[(size_t)e2.x * 32 + lane];
        float2 r3 = in2[(size_t)e3.x * 32 + lane];
        float w0 = __int_as_float(e0.y), w1 = __int_as_float(e1.y);
        float w2 = __int_as_float(e2.y), w3 = __int_as_float(e3.y);
        a0.x = fmaf(w0, r0.x, a0.x); a0.y = fmaf(w0, r0.y, a0.y);
        a1.x = fmaf(w1, r1.x, a1.x); a1.y = fmaf(w1, r1.y, a1.y);
        a2.x = fmaf(w2, r2.x, a2.x); a2.y = fmaf(w2, r2.y, a2.y);
        a3.x = fmaf(w3, r3.x, a3.x); a3.y = fmaf(w3, r3.y, a3.y);
    }
    for (; j < end; j++) {
        int2 e0 = __ldg(&g_cse[j]);
        float w0 = __int_as_float(e0.y);
        float2 r0 = in2[(size_t)e0.x * 32 + lane];
        a0.x = fmaf(w0, r0.x, a0.x); a0.y = fmaf(w0, r0.y, a0.y);
    }
    float2 s;
    s.x = (a0.x + a1.x) + (a2.x + a3.x);
    s.y = (a0.y + a1.y) + (a2.y + a3.y);
    float2* ou = phase ? (float2*)g_tx2 : (float2*)g_tx1;
    ou[(size_t)node * 32 + lane] = s;
}

// fused Cheb-combine + GAT projection + attention dots. 16 nodes per 256-thread block.
__global__ void k_fused(const float* __restrict__ cw, const float* __restrict__ cb,
                        const float* __restrict__ gw, const float* __restrict__ as,
                        const float* __restrict__ ad, int n) {
    __shared__ float s_in[NPB][3][F];     // 12KB
    __shared__ float s_h[NPB][F];         // 4KB
    __shared__ float s_red[2][8][NPB];    // 1KB
    int t = threadIdx.x;
    int base = blockIdx.x * NPB;

    for (int i = t; i < NPB * F; i += 256) {
        int m = i >> 6, c = i & 63;
        int node = base + m;
        if (node < n) {
            s_in[m][0][c] = g_xln[node * F + c];
            s_in[m][1][c] = g_tx1[node * F + c];
            s_in[m][2][c] = g_tx2[node * F + c];
        }
    }
    __syncthreads();

    // Cheb: thread handles output column o for nodes m = g, g+4, g+8, g+12
    int o = t & 63, g = t >> 6;
    float accc[4] = {0.f, 0.f, 0.f, 0.f};
    #pragma unroll 8
    for (int c = 0; c < F; c++) {
        float w0 = cw[c * F + o];
        float w1 = cw[F * F + c * F + o];
        float w2 = cw[2 * F * F + c * F + o];
        #pragma unroll
        for (int q = 0; q < 4; q++) {
            int m = g + 4 * q;
            float a0 = s_in[m][0][c], a1 = s_in[m][1][c];
            float a2 = 2.f * s_in[m][2][c] - a0;
            accc[q] = fmaf(a0, w0, fmaf(a1, w1, fmaf(a2, w2, accc[q])));
        }
    }
    float bias = cb[o];
    #pragma unroll
    for (int q = 0; q < 4; q++)
        s_h[g + 4 * q][o] = leaky(accc[q] + bias, 0.01f);
    __syncthreads();

    // xw: thread computes output column j = t (head j>>6, feature j&63) for all 16 nodes
    int j = t;
    float acc[NPB];
    #pragma unroll
    for (int m = 0; m < NPB; m++) acc[m] = 0.f;
    #pragma unroll 4
    for (int c4 = 0; c4 < F / 4; c4++) {
        float w0 = gw[(c4 * 4 + 0) * 256 + j];
        float w1 = gw[(c4 * 4 + 1) * 256 + j];
        float w2 = gw[(c4 * 4 + 2) * 256 + j];
        float w3 = gw[(c4 * 4 + 3) * 256 + j];
        #pragma unroll
        for (int m = 0; m < NPB; m++) {
            float4 hv = *reinterpret_cast<const float4*>(&s_h[m][c4 * 4]);
            acc[m] = fmaf(hv.x, w0, fmaf(hv.y, w1, fmaf(hv.z, w2, fmaf(hv.w, w3, acc[m]))));
        }
    }

    // write xh as half2 (features 2c', 2c'+1 packed)
    int c = t & 63, h = t >> 6;
    #pragma unroll
    for (int m = 0; m < NPB; m++) {
        float other = __shfl_xor_sync(0xffffffffu, acc[m], 1);
        int node = base + m;
        if (!(c & 1) && node < n) {
            __half2 hv = __floats2half2_rn(acc[m], other);
            g_xh16[(size_t)node * 128 + h * 32 + (c >> 1)] = hv;
        }
    }

    // attention dots
    float asj = as[j], adj = ad[j];
    int lane = t & 31, wid = t >> 5;
    #pragma unroll
    for (int m = 0; m < NPB; m++) {
        float sv = acc[m] * asj, dv = acc[m] * adj;
        #pragma unroll
        for (int off = 16; off; off >>= 1) {
            sv += __shfl_xor_sync(0xffffffffu, sv, off);
            dv += __shfl_xor_sync(0xffffffffu, dv, off);
        }
        if (lane == 0) { s_red[0][wid][m] = sv; s_red[1][wid][m] = dv; }
    }
    __syncthreads();
    if (t < 64) {
        int hh = t >> 4, m = t & 15;
        int node = base + m;
        if (node < n) {
            g_asrc[node * NH + hh] = s_red[0][2 * hh][m] + s_red[0][2 * hh + 1][m];
            g_adst[node * NH + hh] = s_red[1][2 * hh][m] + s_red[1][2 * hh + 1][m];
        }
    }
}

// fused GAT, single edge sweep. warp per node.
// lane owns head (lane>>3), features (lane&7)*8..+7 -> one LDG.128 per edge per lane.
__global__ void k_gat(const float* __restrict__ gb, float* __restrict__ out, int n) {
    __shared__ float4 s_ex[8][32];
    __shared__ int    s_s[8][32];
    int wid = threadIdx.x >> 5;
    int node = (blockIdx.x * blockDim.x + threadIdx.x) >> 5;
    int lane = threadIdx.x & 31;
    if (node >= n) return;
    int beg = g_rowptr[node], end = g_rowptr[node + 1];
    int myh = lane >> 3;

    const float4* pa = reinterpret_cast<const float4*>(g_asrc);
    const float4* pd = reinterpret_cast<const float4*>(g_adst);
    float4 adv = pd[node];
    float4 asn = pa[node];
    float selfex[NH];
    selfex[0] = __expf(leaky(asn.x + adv.x, 0.2f));
    selfex[1] = __expf(leaky(asn.y + adv.y, 0.2f));
    selfex[2] = __expf(leaky(asn.z + adv.z, 0.2f));
    selfex[3] = __expf(leaky(asn.w + adv.w, 0.2f));

    const uint4* xh = reinterpret_cast<const uint4*>(g_xh16);
    float a[8];
    {   // self term
        uint4 v = __ldg(&xh[(size_t)node * 32 + lane]);
        const __half2* h2 = reinterpret_cast<const __half2*>(&v);
        float alpha = selfex[myh];
        #pragma unroll
        for (int i = 0; i < 4; i++) {
            float2 f = __half22float2(h2[i]);
            a[2 * i]     = alpha * f.x;
            a[2 * i + 1] = alpha * f.y;
        }
    }
    float den[NH] = {0.f, 0.f, 0.f, 0.f};

    for (int j0 = beg; j0 < end; j0 += 32) {
        int cnt = min(32, end - j0);
        float4 ex = make_float4(0.f, 0.f, 0.f, 0.f);
        int s = 0;
        if (lane < cnt) {
            s = __ldg(&g_cse[j0 + lane]).x;
            float4 av = pa[s];
            ex.x = __expf(leaky(av.x + adv.x, 0.2f));
            ex.y = __expf(leaky(av.y + adv.y, 0.2f));
            ex.z = __expf(leaky(av.z + adv.z, 0.2f));
            ex.w = __expf(leaky(av.w + adv.w, 0.2f));
            den[0] += ex.x; den[1] += ex.y; den[2] += ex.z; den[3] += ex.w;
        }
        s_ex[wid][lane] = ex;
        s_s[wid][lane] = s;
        __syncwarp();
        #pragma unroll 2
        for (int k = 0; k < cnt; k++) {
            int sk = s_s[wid][k];
            float alpha = reinterpret_cast<const float*>(&s_ex[wid][k])[myh];
            uint4 v = __ldg(&xh[(size_t)sk * 32 + lane]);
            const __half2* h2 = reinterpret_cast<const __half2*>(&v);
            #pragma unroll
            for (int i = 0; i < 4; i++) {
                float2 f = __half22float2(h2[i]);
                a[2 * i]     = fmaf(alpha, f.x, a[2 * i]);
                a[2 * i + 1] = fmaf(alpha, f.y, a[2 * i + 1]);
            }
        }
        __syncwarp();
    }

    #pragma unroll
    for (int o = 16; o; o >>= 1)
        #pragma unroll
        for (int h = 0; h < NH; h++)
            den[h] += __shfl_xor_sync(0xffffffffu, den[h], o);
    float iv = 1.f / (den[myh] + selfex[myh] + 1e-16f);

    // normalize by own head's denom, then sum across heads (lanes ^8, ^16)
    #pragma unroll
    for (int i = 0; i < 8; i++) {
        float r = a[i] * iv;
        r += __shfl_xor_sync(0xffffffffu, r, 8);
        r += __shfl_xor_sync(0xffffffffu, r, 16);
        a[i] = r;
    }
    if (lane < 8) {
        float* op = out + (size_t)node * F + lane * 8;
        #pragma unroll
        for (int i = 0; i < 8; i++)
            op[i] = leaky(0.25f * a[i] + gb[lane * 8 + i], 0.01f);
    }
}

// ---------------- launch ----------------
extern "C" void kernel_launch(void* const* d_in, const int* in_sizes, int n_in,
                              void* d_out, int out_size) {
    const float* x      = (const float*)d_in[0];
    const int*   ei     = (const int*)  d_in[1];
    const float* ea     = (const float*)d_in[2];
    const float* lng    = (const float*)d_in[3];
    const float* lnb    = (const float*)d_in[4];
    const float* cw     = (const float*)d_in[5];
    const float* cb     = (const float*)d_in[6];
    const float* gw     = (const float*)d_in[7];
    const float* as     = (const float*)d_in[8];
    const float* ad     = (const float*)d_in[9];
    const float* gb     = (const float*)d_in[10];
    float* out = (float*)d_out;

    const int n = in_sizes[0] / F;        // 50000
    const int e = in_sizes[2];            // 800000
    const int* src = ei;
    const int* dst = ei + e;

    const int TB = 256;
    auto cdiv = [](long long a, long long b) { return (int)((a + b - 1) / b); };
    int nb = cdiv(n, 256);

    k_init  <<<cdiv(n, TB), TB>>>(n);
    k_ln    <<<cdiv((long long)n * 32, TB), TB>>>(x, lng, lnb, n);
    k_degcnt<<<cdiv(e, TB), TB>>>(src, dst, ea, e);
    k_scan1 <<<nb, 256>>>(n);
    k_scan2 <<<1, 256>>>(nb);
    k_scan3 <<<cdiv(n, TB), TB>>>(n, e);
    k_fill  <<<cdiv(e, TB), TB>>>(src, dst, ea, e);
    k_prop  <<<cdiv((long long)n * 32, TB), TB>>>(n, 0);
    k_prop  <<<cdiv((long long)n * 32, TB), TB>>>(n, 1);
    k_fused <<<cdiv(n, NPB), 256>>>(cw, cb, gw, as, ad, n);
    k_gat   <<<cdiv((long long)n * 32, TB), TB>>>(gb, out, n);
}

// round 9
// speedup vs baseline: 1.1800x; 1.0966x over previous
#include <cuda_runtime.h>
#include <cuda_fp16.h>
#include <math.h>

#define NMAX 50000
#define EMAX 800000
#define F 64
#define NH 4

// ---------------- scratch (device globals; referenced ONLY from device code) ----------------
__device__ float   g_xln[NMAX * F];           // Tx0 (layernormed x)
__device__ float   g_tx1[NMAX * F];           // Tx1 = L_hat @ Tx0
__device__ float   g_tx2[NMAX * F];           // L_hat @ Tx1
__device__ __half2 g_xh16[(size_t)NMAX * 128];// projected features, [node][head][feat/2]
__device__ float   g_asrc[NMAX * NH];
__device__ float   g_adst[NMAX * NH];
__device__ float   g_deg[NMAX];
__device__ float   g_dinv[NMAX];
__device__ int     g_cnt[NMAX];
__device__ int     g_loc[NMAX];
__device__ int     g_bsum[256];
__device__ int     g_rowptr[NMAX + 1];
__device__ int     g_cursor[NMAX];
__device__ int2    g_cse[EMAX];               // CSR: (src, weight-as-int)
__device__ __half  g_wct[64 * 192];           // Cheb weights, transposed: [n][3c+j]
__device__ __half  g_wgt[256 * 64];           // GAT weights, transposed: [n][c]

__device__ __forceinline__ float leaky(float x, float s) {
    return x >= 0.f ? x : s * x;
}

__device__ __forceinline__ void mma16816(float* c, unsigned a0, unsigned a1,
                                         unsigned a2, unsigned a3,
                                         unsigned b0, unsigned b1) {
    asm volatile(
        "mma.sync.aligned.m16n8k16.row.col.f32.f16.f16.f32 "
        "{%0,%1,%2,%3}, {%4,%5,%6,%7}, {%8,%9}, {%0,%1,%2,%3};\n"
        : "+f"(c[0]), "+f"(c[1]), "+f"(c[2]), "+f"(c[3])
        : "r"(a0), "r"(a1), "r"(a2), "r"(a3), "r"(b0), "r"(b1));
}

// ---------------- kernels ----------------
__global__ void k_init(int n) {
    int i = blockIdx.x * blockDim.x + threadIdx.x;
    if (i < n) { g_deg[i] = 0.f; g_cnt[i] = 0; }
}

// one-time weight transpose + fp16 convert
__global__ void k_prep(const float* __restrict__ cw, const float* __restrict__ gw) {
    int i = blockIdx.x * blockDim.x + threadIdx.x;
    if (i < 64 * 192) {
        int nn = i / 192, k = i % 192;
        int c = k / 3, j = k % 3;
        g_wct[i] = __float2half(cw[j * 4096 + c * 64 + nn]);
    } else if (i < 64 * 192 + 256 * 64) {
        int q = i - 64 * 192;
        int nn = q / 64, c = q % 64;
        g_wgt[q] = __float2half(gw[c * 256 + nn]);
    }
}

// one warp per node; lane handles c and c+32
__global__ void k_ln(const float* __restrict__ x, const float* __restrict__ gamma,
                     const float* __restrict__ beta, int n) {
    int warp = (blockIdx.x * blockDim.x + threadIdx.x) >> 5;
    int lane = threadIdx.x & 31;
    if (warp >= n) return;
    const float* xr = x + (size_t)warp * F;
    float a = xr[lane], b = xr[lane + 32];
    float s = a + b, sq = a * a + b * b;
    #pragma unroll
    for (int o = 16; o; o >>= 1) {
        s  += __shfl_xor_sync(0xffffffffu, s,  o);
        sq += __shfl_xor_sync(0xffffffffu, sq, o);
    }
    float mu  = s * (1.f / 64.f);
    float var = sq * (1.f / 64.f) - mu * mu;
    float r = rsqrtf(var + 1e-5f);
    g_xln[warp * F + lane]      = (a - mu) * r * gamma[lane]      + beta[lane];
    g_xln[warp * F + lane + 32] = (b - mu) * r * gamma[lane + 32] + beta[lane + 32];
}

__global__ void k_degcnt(const int* __restrict__ src, const int* __restrict__ dst,
                         const float* __restrict__ ea, int e) {
    int i = blockIdx.x * blockDim.x + threadIdx.x;
    if (i >= e) return;
    atomicAdd(&g_deg[src[i]], ea[i]);
    atomicAdd(&g_cnt[dst[i]], 1);
}

// ---- 3-phase parallel exclusive scan of g_cnt ----
__global__ void k_scan1(int n) {
    __shared__ int sm[256];
    int t = threadIdx.x;
    int i = blockIdx.x * 256 + t;
    int v = (i < n) ? g_cnt[i] : 0;
    sm[t] = v;
    __syncthreads();
    for (int o = 1; o < 256; o <<= 1) {
        int u = (t >= o) ? sm[t - o] : 0;
        __syncthreads();
        sm[t] += u;
        __syncthreads();
    }
    if (i < n) g_loc[i] = sm[t] - v;
    if (t == 255) g_bsum[blockIdx.x] = sm[255];
}

__global__ void k_scan2(int nb) {
    __shared__ int sm[256];
    int t = threadIdx.x;
    int v = (t < nb) ? g_bsum[t] : 0;
    sm[t] = v;
    __syncthreads();
    for (int o = 1; o < 256; o <<= 1) {
        int u = (t >= o) ? sm[t - o] : 0;
        __syncthreads();
        sm[t] += u;
        __syncthreads();
    }
    if (t < nb) g_bsum[t] = sm[t] - v;
}

__global__ void k_scan3(int n, int e) {
    int i = blockIdx.x * blockDim.x + threadIdx.x;
    if (i < n) {
        int r = g_bsum[i >> 8] + g_loc[i];
        g_rowptr[i] = r;
        g_cursor[i] = r;
        float d = g_deg[i];
        g_dinv[i] = d > 0.f ? rsqrtf(d) : 0.f;
    }
    if (i == 0) g_rowptr[n] = e;
}

__global__ void k_fill(const int* __restrict__ src, const int* __restrict__ dst,
                       const float* __restrict__ ea, int e) {
    int i = blockIdx.x * blockDim.x + threadIdx.x;
    if (i >= e) return;
    int s = src[i], d = dst[i];
    int pos = atomicAdd(&g_cursor[d], 1);
    float w = -(g_dinv[s] * ea[i] * g_dinv[d]);
    g_cse[pos] = make_int2(s, __float_as_int(w));
}

// gather propagation; warp per node; float2 per lane; 4-edge ILP
__global__ void k_prop(int n, int phase) {
    int node = (blockIdx.x * blockDim.x + threadIdx.x) >> 5;
    int lane = threadIdx.x & 31;
    if (node >= n) return;
    const float2* in2 = phase ? (const float2*)g_tx1 : (const float2*)g_xln;
    int beg = g_rowptr[node], end = g_rowptr[node + 1];
    float2 a0 = {0.f, 0.f}, a1 = {0.f, 0.f}, a2 = {0.f, 0.f}, a3 = {0.f, 0.f};
    int j = beg;
    for (; j + 4 <= end; j += 4) {
        int2 e0 = __ldg(&g_cse[j]),     e1 = __ldg(&g_cse[j + 1]);
        int2 e2 = __ldg(&g_cse[j + 2]), e3 = __ldg(&g_cse[j + 3]);
        float2 r0 = in2[(size_t)e0.x * 32 + lane];
        float2 r1 = in2[(size_t)e1.x * 32 + lane];
        float2 r2 = in2[(size_t)e2.x * 32 + lane];
        float2 r3 = in2[(size_t)e3.x * 32 + lane];
        float w0 = __int_as_float(e0.y), w1 = __int_as_float(e1.y);
        float w2 = __int_as_float(e2.y), w3 = __int_as_float(e3.y);
        a0.x = fmaf(w0, r0.x, a0.x); a0.y = fmaf(w0, r0.y, a0.y);
        a1.x = fmaf(w1, r1.x, a1.x); a1.y = fmaf(w1, r1.y, a1.y);
        a2.x = fmaf(w2, r2.x, a2.x); a2.y = fmaf(w2, r2.y, a2.y);
        a3.x = fmaf(w3, r3.x, a3.x); a3.y = fmaf(w3, r3.y, a3.y);
    }
    for (; j < end; j++) {
        int2 e0 = __ldg(&g_cse[j]);
        float w0 = __int_as_float(e0.y);
        float2 r0 = in2[(size_t)e0.x * 32 + lane];
        a0.x = fmaf(w0, r0.x, a0.x); a0.y = fmaf(w0, r0.y, a0.y);
    }
    float2 s;
    s.x = (a0.x + a1.x) + (a2.x + a3.x);
    s.y = (a0.y + a1.y) + (a2.y + a3.y);
    float2* ou = phase ? (float2*)g_tx2 : (float2*)g_tx1;
    ou[(size_t)node * 32 + lane] = s;
}

// tensor-core fused: Cheb GEMM (fp16 mma, fp32 accum) -> H -> GAT projection GEMM
// -> xh (fp16) + attention dots. 128 nodes per 256-thread block (8 warps x 16 rows).
__global__ void __launch_bounds__(256) k_mma(const float* __restrict__ cb,
                                             const float* __restrict__ as,
                                             const float* __restrict__ ad, int n) {
    __shared__ __align__(16) char sbuf[40960];
    __shared__ float s_cb[64];
    __shared__ float s_as[256], s_ad[256];
    __half* sA  = (__half*)sbuf;                 // phase1: [128][104]
    unsigned* sW1u = (unsigned*)(sbuf + 26624);  // phase1: [64][52] uints
    unsigned* sHu  = (unsigned*)sbuf;            // phase2: [128][36] uints
    unsigned* sW2u = (unsigned*)(sbuf + 18432);  // phase2: [128][36] uints

    int t = threadIdx.x;
    int base = blockIdx.x * 128;
    int lane = t & 31, w = t >> 5;
    int g = lane >> 2, tt = lane & 3;

    if (t < 64) s_cb[t] = cb[t];
    s_as[t] = as[t];
    s_ad[t] = ad[t];

    float acc1[8][4];
    #pragma unroll
    for (int i = 0; i < 8; i++)
        #pragma unroll
        for (int q = 0; q < 4; q++) acc1[i][q] = 0.f;

    // ---- GEMM1: H = leaky(T @ Wc + cb), T = [Tx0|Tx1|Tx2] K-interleaved (k=3c+j) ----
    #pragma unroll
    for (int kh = 0; kh < 2; kh++) {
        __syncthreads();
        // stage A: 128 nodes x 32 c-values x 3 terms
        #pragma unroll
        for (int i = 0; i < 16; i++) {
            int idx = t + 256 * i;
            int m = idx >> 5, cl = idx & 31;
            int c = (kh << 5) + cl;
            int node = base + m;
            float t0 = 0.f, t1 = 0.f, t2 = 0.f;
            if (node < n) {
                t0 = g_xln[node * 64 + c];
                t1 = g_tx1[node * 64 + c];
                t2 = 2.f * g_tx2[node * 64 + c] - t0;
            }
            __half* p = sA + m * 104 + 3 * cl;
            p[0] = __float2half(t0);
            p[1] = __float2half(t1);
            p[2] = __float2half(t2);
        }
        // stage W1 half (64 n x 96 k as uints)
        const unsigned* wct = (const unsigned*)g_wct;   // [64][96] uints
        #pragma unroll
        for (int i = 0; i < 12; i++) {
            int idx = t + 256 * i;             // 0..3071
            int nn = idx / 48, c2 = idx % 48;
            sW1u[nn * 52 + c2] = wct[nn * 96 + 48 * kh + c2];
        }
        __syncthreads();
        const unsigned* Au = (const unsigned*)sA;       // [128][52]
        #pragma unroll
        for (int ks = 0; ks < 6; ks++) {
            int arow = 16 * w + g;
            unsigned a0 = Au[arow * 52 + 8 * ks + tt];
            unsigned a1 = Au[(arow + 8) * 52 + 8 * ks + tt];
            unsigned a2 = Au[arow * 52 + 8 * ks + tt + 4];
            unsigned a3 = Au[(arow + 8) * 52 + 8 * ks + tt + 4];
            #pragma unroll
            for (int ns = 0; ns < 8; ns++) {
                int nc = 8 * ns + g;
                unsigned b0 = sW1u[nc * 52 + 8 * ks + tt];
                unsigned b1 = sW1u[nc * 52 + 8 * ks + tt + 4];
                mma16816(acc1[ns], a0, a1, a2, a3, b0, b1);
            }
        }
    }

    // ---- bias + leaky -> H in smem (fp16) ----
    __syncthreads();
    #pragma unroll
    for (int ns = 0; ns < 8; ns++) {
        int col = 8 * ns + 2 * tt;
        float b0f = s_cb[col], b1f = s_cb[col + 1];
        int r0 = 16 * w + g;
        __half2 h01 = __floats2half2_rn(leaky(acc1[ns][0] + b0f, 0.01f),
                                        leaky(acc1[ns][1] + b1f, 0.01f));
        __half2 h23 = __floats2half2_rn(leaky(acc1[ns][2] + b0f, 0.01f),
                                        leaky(acc1[ns][3] + b1f, 0.01f));
        sHu[r0 * 36 + (col >> 1)]       = *(unsigned*)&h01;
        sHu[(r0 + 8) * 36 + (col >> 1)] = *(unsigned*)&h23;
    }

    // ---- GEMM2: XH = H @ Wg (two 128-col halves) + attention dots ----
    const unsigned* wgt = (const unsigned*)g_wgt;       // [256][32] uints
    int node0 = base + 16 * w + g, node1 = node0 + 8;
    #pragma unroll
    for (int nh = 0; nh < 2; nh++) {
        __syncthreads();
        #pragma unroll
        for (int i = 0; i < 16; i++) {
            int idx = t + 256 * i;             // 0..4095
            int nc = idx >> 5, c2 = idx & 31;
            sW2u[nc * 36 + c2] = wgt[(128 * nh + nc) * 32 + c2];
        }
        __syncthreads();
        float acc2[16][4];
        #pragma unroll
        for (int i = 0; i < 16; i++)
            #pragma unroll
            for (int q = 0; q < 4; q++) acc2[i][q] = 0.f;
        #pragma unroll
        for (int ks = 0; ks < 4; ks++) {
            int arow = 16 * w + g;
            unsigned a0 = sHu[arow * 36 + 8 * ks + tt];
            unsigned a1 = sHu[(arow + 8) * 36 + 8 * ks + tt];
            unsigned a2 = sHu[arow * 36 + 8 * ks + tt + 4];
            unsigned a3 = sHu[(arow + 8) * 36 + 8 * ks + tt + 4];
            #pragma unroll
            for (int ns = 0; ns < 16; ns++) {
                int nc = 8 * ns + g;
                unsigned b0 = sW2u[nc * 36 + 8 * ks + tt];
                unsigned b1 = sW2u[nc * 36 + 8 * ks + tt + 4];
                mma16816(acc2[ns], a0, a1, a2, a3, b0, b1);
            }
        }
        // store XH (fp16) + accumulate attention partials
        float sv0 = 0.f, sv1 = 0.f, dv0 = 0.f, dv1 = 0.f;   // head 0 of this half
        float sw0 = 0.f, sw1 = 0.f, dw0 = 0.f, dw1 = 0.f;   // head 1 of this half
        #pragma unroll
        for (int ns = 0; ns < 16; ns++) {
            int col = 128 * nh + 8 * ns + 2 * tt;
            float as0 = s_as[col], as1 = s_as[col + 1];
            float ad0 = s_ad[col], ad1 = s_ad[col + 1];
            float c0 = acc2[ns][0], c1 = acc2[ns][1];
            float c2v = acc2[ns][2], c3 = acc2[ns][3];
            if (node0 < n) {
                __half2 h01 = __floats2half2_rn(c0, c1);
                g_xh16[(size_t)node0 * 128 + (col >> 1)] = h01;
            }
            if (node1 < n) {
                __half2 h23 = __floats2half2_rn(c2v, c3);
                g_xh16[(size_t)node1 * 128 + (col >> 1)] = h23;
            }
            if (ns < 8) {
                sv0 = fmaf(c0, as0, fmaf(c1, as1, sv0));
                dv0 = fmaf(c0, ad0, fmaf(c1, ad1, dv0));
                sv1 = fmaf(c2v, as0, fmaf(c3, as1, sv1));
                dv1 = fmaf(c2v, ad0, fmaf(c3, ad1, dv1));
            } else {
                sw0 = fmaf(c0, as0, fmaf(c1, as1, sw0));
                dw0 = fmaf(c0, ad0, fmaf(c1, ad1, dw0));
                sw1 = fmaf(c2v, as0, fmaf(c3, as1, sw1));
                dw1 = fmaf(c2v, ad0, fmaf(c3, ad1, dw1));
            }
        }
        #pragma unroll
        for (int o = 1; o <= 2; o <<= 1) {
            sv0 += __shfl_xor_sync(0xffffffffu, sv0, o);
            sv1 += __shfl_xor_sync(0xffffffffu, sv1, o);
            dv0 += __shfl_xor_sync(0xffffffffu, dv0, o);
            dv1 += __shfl_xor_sync(0xffffffffu, dv1, o);
            sw0 += __shfl_xor_sync(0xffffffffu, sw0, o);
            sw1 += __shfl_xor_sync(0xffffffffu, sw1, o);
            dw0 += __shfl_xor_sync(0xffffffffu, dw0, o);
            dw1 += __shfl_xor_sync(0xffffffffu, dw1, o);
        }
        if (tt == 0) {
            int hg = 2 * nh;
            if (node0 < n) {
                g_asrc[node0 * 4 + hg]     = sv0;
                g_adst[node0 * 4 + hg]     = dv0;
                g_asrc[node0 * 4 + hg + 1] = sw0;
                g_adst[node0 * 4 + hg + 1] = dw0;
            }
            if (node1 < n) {
                g_asrc[node1 * 4 + hg]     = sv1;
                g_adst[node1 * 4 + hg]     = dv1;
                g_asrc[node1 * 4 + hg + 1] = sw1;
                g_adst[node1 * 4 + hg + 1] = dw1;
            }
        }
    }
}

// fused GAT, single edge sweep. warp per node.
// lane owns head (lane>>3), features (lane&7)*8..+7 -> one LDG.128 per edge per lane.
__global__ void k_gat(const float* __restrict__ gb, float* __restrict__ out, int n) {
    __shared__ float4 s_ex[8][32];
    __shared__ int    s_s[8][32];
    int wid = threadIdx.x >> 5;
    int node = (blockIdx.x * blockDim.x + threadIdx.x) >> 5;
    int lane = threadIdx.x & 31;
    if (node >= n) return;
    int beg = g_rowptr[node], end = g_rowptr[node + 1];
    int myh = lane >> 3;

    const float4* pa = reinterpret_cast<const float4*>(g_asrc);
    const float4* pd = reinterpret_cast<const float4*>(g_adst);
    float4 adv = pd[node];
    float4 asn = pa[node];
    float selfex[NH];
    selfex[0] = __expf(leaky(asn.x + adv.x, 0.2f));
    selfex[1] = __expf(leaky(asn.y + adv.y, 0.2f));
    selfex[2] = __expf(leaky(asn.z + adv.z, 0.2f));
    selfex[3] = __expf(leaky(asn.w + adv.w, 0.2f));

    const uint4* xh = reinterpret_cast<const uint4*>(g_xh16);
    float a[8];
    {   // self term
        uint4 v = __ldg(&xh[(size_t)node * 32 + lane]);
        const __half2* h2 = reinterpret_cast<const __half2*>(&v);
        float alpha = selfex[myh];
        #pragma unroll
        for (int i = 0; i < 4; i++) {
            float2 f = __half22float2(h2[i]);
            a[2 * i]     = alpha * f.x;
            a[2 * i + 1] = alpha * f.y;
        }
    }
    float den[NH] = {0.f, 0.f, 0.f, 0.f};

    for (int j0 = beg; j0 < end; j0 += 32) {
        int cnt = min(32, end - j0);
        float4 ex = make_float4(0.f, 0.f, 0.f, 0.f);
        int s = 0;
        if (lane < cnt) {
            s = __ldg(&g_cse[j0 + lane]).x;
            float4 av = pa[s];
            ex.x = __expf(leaky(av.x + adv.x, 0.2f));
            ex.y = __expf(leaky(av.y + adv.y, 0.2f));
            ex.z = __expf(leaky(av.z + adv.z, 0.2f));
            ex.w = __expf(leaky(av.w + adv.w, 0.2f));
            den[0] += ex.x; den[1] += ex.y; den[2] += ex.z; den[3] += ex.w;
        }
        s_ex[wid][lane] = ex;
        s_s[wid][lane] = s;
        __syncwarp();
        #pragma unroll 2
        for (int k = 0; k < cnt; k++) {
            int sk = s_s[wid][k];
            float alpha = reinterpret_cast<const float*>(&s_ex[wid][k])[myh];
            uint4 v = __ldg(&xh[(size_t)sk * 32 + lane]);
            const __half2* h2 = reinterpret_cast<const __half2*>(&v);
            #pragma unroll
            for (int i = 0; i < 4; i++) {
                float2 f = __half22float2(h2[i]);
                a[2 * i]     = fmaf(alpha, f.x, a[2 * i]);
                a[2 * i + 1] = fmaf(alpha, f.y, a[2 * i + 1]);
            }
        }
        __syncwarp();
    }

    #pragma unroll
    for (int o = 16; o; o >>= 1)
        #pragma unroll
        for (int h = 0; h < NH; h++)
            den[h] += __shfl_xor_sync(0xffffffffu, den[h], o);
    float iv = 1.f / (den[myh] + selfex[myh] + 1e-16f);

    #pragma unroll
    for (int i = 0; i < 8; i++) {
        float r = a[i] * iv;
        r += __shfl_xor_sync(0xffffffffu, r, 8);
        r += __shfl_xor_sync(0xffffffffu, r, 16);
        a[i] = r;
    }
    if (lane < 8) {
        float* op = out + (size_t)node * F + lane * 8;
        #pragma unroll
        for (int i = 0; i < 8; i++)
            op[i] = leaky(0.25f * a[i] + gb[lane * 8 + i], 0.01f);
    }
}

// ---------------- launch ----------------
extern "C" void kernel_launch(void* const* d_in, const int* in_sizes, int n_in,
                              void* d_out, int out_size) {
    const float* x      = (const float*)d_in[0];
    const int*   ei     = (const int*)  d_in[1];
    const float* ea     = (const float*)d_in[2];
    const float* lng    = (const float*)d_in[3];
    const float* lnb    = (const float*)d_in[4];
    const float* cw     = (const float*)d_in[5];
    const float* cb     = (const float*)d_in[6];
    const float* gw     = (const float*)d_in[7];
    const float* as     = (const float*)d_in[8];
    const float* ad     = (const float*)d_in[9];
    const float* gb     = (const float*)d_in[10];
    float* out = (float*)d_out;

    const int n = in_sizes[0] / F;        // 50000
    const int e = in_sizes[2];            // 800000
    const int* src = ei;
    const int* dst = ei + e;

    const int TB = 256;
    auto cdiv = [](long long a, long long b) { return (int)((a + b - 1) / b); };
    int nb = cdiv(n, 256);

    k_init  <<<cdiv(n, TB), TB>>>(n);
    k_prep  <<<cdiv(64 * 192 + 256 * 64, TB), TB>>>(cw, gw);
    k_ln    <<<cdiv((long long)n * 32, TB), TB>>>(x, lng, lnb, n);
    k_degcnt<<<cdiv(e, TB), TB>>>(src, dst, ea, e);
    k_scan1 <<<nb, 256>>>(n);
    k_scan2 <<<1, 256>>>(nb);
    k_scan3 <<<cdiv(n, TB), TB>>>(n, e);
    k_fill  <<<cdiv(e, TB), TB>>>(src, dst, ea, e);
    k_prop  <<<cdiv((long long)n * 32, TB), TB>>>(n, 0);
    k_prop  <<<cdiv((long long)n * 32, TB), TB>>>(n, 1);
    k_mma   <<<cdiv(n, 128), 256>>>(cb, as, ad, n);
    k_gat   <<<cdiv((long long)n * 32, TB), TB>>>(gb, out, n);
}

// round 10
// speedup vs baseline: 1.5147x; 1.2837x over previous
#include <cuda_runtime.h>
#include <cuda_fp16.h>
#include <math.h>

#define NMAX 50000
#define NPAD 50176      // NMAX rounded up to multiple of 128
#define EMAX 800000
#define F 64
#define NH 4

// ---------------- scratch (device globals; referenced ONLY from device code) ----------------
__device__ float    g_xln[NMAX * F];
__device__ float    g_tx1[NMAX * F];
__device__ float    g_tx2[NMAX * F];
__device__ unsigned g_h16[(size_t)NPAD * 32];    // H fp16, [node][feat/2] (128B rows)
__device__ unsigned g_M16[(size_t)NPAD * 128];   // M fp16, [node][head*32 + feat/2]
__device__ float    g_asrc[NMAX * NH];
__device__ float    g_adst[NMAX * NH];
__device__ float    g_deg[NMAX];
__device__ float    g_dinv[NMAX];
__device__ int      g_cnt[NMAX];
__device__ int      g_loc[NMAX];
__device__ int      g_bsum[256];
__device__ int      g_rowptr[NMAX + 1];
__device__ int      g_cursor[NMAX];
__device__ int2     g_cse[EMAX];                 // CSR: (src, weight-as-int)
__device__ __half   g_wct[64 * 192];             // Cheb weights, transposed [n][3c+j]
__device__ __half   g_wg2[64 * 256];             // 0.25*stacked Wg, [n_out][h*64+c]
__device__ float    g_vs[NH * 64];               // Wg_h^T att_src_h
__device__ float    g_vd[NH * 64];               // Wg_h^T att_dst_h

__device__ __forceinline__ float leaky(float x, float s) {
    return x >= 0.f ? x : s * x;
}

__device__ __forceinline__ void mma16816(float* c, unsigned a0, unsigned a1,
                                         unsigned a2, unsigned a3,
                                         unsigned b0, unsigned b1) {
    asm volatile(
        "mma.sync.aligned.m16n8k16.row.col.f32.f16.f16.f32 "
        "{%0,%1,%2,%3}, {%4,%5,%6,%7}, {%8,%9}, {%0,%1,%2,%3};\n"
        : "+f"(c[0]), "+f"(c[1]), "+f"(c[2]), "+f"(c[3])
        : "r"(a0), "r"(a1), "r"(a2), "r"(a3), "r"(b0), "r"(b1));
}

// ---------------- kernels ----------------
__global__ void k_init(int n) {
    int i = blockIdx.x * blockDim.x + threadIdx.x;
    if (i < n) { g_deg[i] = 0.f; g_cnt[i] = 0; }
}

// one-time weight prep: transposed fp16 Wc, stacked fp16 Wg2, vs/vd vectors
__global__ void k_prep(const float* __restrict__ cw, const float* __restrict__ gw,
                       const float* __restrict__ as, const float* __restrict__ ad) {
    int i = blockIdx.x * blockDim.x + threadIdx.x;
    if (i < 64 * 192) {
        int nn = i / 192, k = i % 192;
        int c = k / 3, j = k % 3;
        g_wct[i] = __float2half(cw[j * 4096 + c * 64 + nn]);
    } else if (i < 64 * 192 + 64 * 256) {
        int q = i - 64 * 192;
        int nn = q >> 8, k = q & 255;
        int h = k >> 6, c = k & 63;
        g_wg2[q] = __float2half(0.25f * gw[c * 256 + h * 64 + nn]);
    } else if (i < 64 * 192 + 64 * 256 + 512) {
        int q = i - 64 * 192 - 64 * 256;   // 0..511
        int isd = q >> 8, h = (q >> 6) & 3, c = q & 63;
        const float* av = isd ? ad : as;
        float acc = 0.f;
        for (int f = 0; f < 64; f++)
            acc = fmaf(gw[c * 256 + h * 64 + f], av[h * 64 + f], acc);
        if (isd) g_vd[h * 64 + c] = acc; else g_vs[h * 64 + c] = acc;
    }
}

// one warp per node; lane handles c and c+32
__global__ void k_ln(const float* __restrict__ x, const float* __restrict__ gamma,
                     const float* __restrict__ beta, int n) {
    int warp = (blockIdx.x * blockDim.x + threadIdx.x) >> 5;
    int lane = threadIdx.x & 31;
    if (warp >= n) return;
    const float* xr = x + (size_t)warp * F;
    float a = xr[lane], b = xr[lane + 32];
    float s = a + b, sq = a * a + b * b;
    #pragma unroll
    for (int o = 16; o; o >>= 1) {
        s  += __shfl_xor_sync(0xffffffffu, s,  o);
        sq += __shfl_xor_sync(0xffffffffu, sq, o);
    }
    float mu  = s * (1.f / 64.f);
    float var = sq * (1.f / 64.f) - mu * mu;
    float r = rsqrtf(var + 1e-5f);
    g_xln[warp * F + lane]      = (a - mu) * r * gamma[lane]      + beta[lane];
    g_xln[warp * F + lane + 32] = (b - mu) * r * gamma[lane + 32] + beta[lane + 32];
}

__global__ void k_degcnt(const int* __restrict__ src, const int* __restrict__ dst,
                         const float* __restrict__ ea, int e) {
    int i = blockIdx.x * blockDim.x + threadIdx.x;
    if (i >= e) return;
    atomicAdd(&g_deg[src[i]], ea[i]);
    atomicAdd(&g_cnt[dst[i]], 1);
}

// ---- 3-phase parallel exclusive scan of g_cnt ----
__global__ void k_scan1(int n) {
    __shared__ int sm[256];
    int t = threadIdx.x;
    int i = blockIdx.x * 256 + t;
    int v = (i < n) ? g_cnt[i] : 0;
    sm[t] = v;
    __syncthreads();
    for (int o = 1; o < 256; o <<= 1) {
        int u = (t >= o) ? sm[t - o] : 0;
        __syncthreads();
        sm[t] += u;
        __syncthreads();
    }
    if (i < n) g_loc[i] = sm[t] - v;
    if (t == 255) g_bsum[blockIdx.x] = sm[255];
}

__global__ void k_scan2(int nb) {
    __shared__ int sm[256];
    int t = threadIdx.x;
    int v = (t < nb) ? g_bsum[t] : 0;
    sm[t] = v;
    __syncthreads();
    for (int o = 1; o < 256; o <<= 1) {
        int u = (t >= o) ? sm[t - o] : 0;
        __syncthreads();
        sm[t] += u;
        __syncthreads();
    }
    if (t < nb) g_bsum[t] = sm[t] - v;
}

__global__ void k_scan3(int n, int e) {
    int i = blockIdx.x * blockDim.x + threadIdx.x;
    if (i < n) {
        int r = g_bsum[i >> 8] + g_loc[i];
        g_rowptr[i] = r;
        g_cursor[i] = r;
        float d = g_deg[i];
        g_dinv[i] = d > 0.f ? rsqrtf(d) : 0.f;
    }
    if (i == 0) g_rowptr[n] = e;
}

__global__ void k_fill(const int* __restrict__ src, const int* __restrict__ dst,
                       const float* __restrict__ ea, int e) {
    int i = blockIdx.x * blockDim.x + threadIdx.x;
    if (i >= e) return;
    int s = src[i], d = dst[i];
    int pos = atomicAdd(&g_cursor[d], 1);
    float w = -(g_dinv[s] * ea[i] * g_dinv[d]);
    g_cse[pos] = make_int2(s, __float_as_int(w));
}

// gather propagation; warp per node; float2 per lane; 4-edge ILP
__global__ void k_prop(int n, int phase) {
    int node = (blockIdx.x * blockDim.x + threadIdx.x) >> 5;
    int lane = threadIdx.x & 31;
    if (node >= n) return;
    const float2* in2 = phase ? (const float2*)g_tx1 : (const float2*)g_xln;
    int beg = g_rowptr[node], end = g_rowptr[node + 1];
    float2 a0 = {0.f, 0.f}, a1 = {0.f, 0.f}, a2 = {0.f, 0.f}, a3 = {0.f, 0.f};
    int j = beg;
    for (; j + 4 <= end; j += 4) {
        int2 e0 = __ldg(&g_cse[j]),     e1 = __ldg(&g_cse[j + 1]);
        int2 e2 = __ldg(&g_cse[j + 2]), e3 = __ldg(&g_cse[j + 3]);
        float2 r0 = in2[(size_t)e0.x * 32 + lane];
        float2 r1 = in2[(size_t)e1.x * 32 + lane];
        float2 r2 = in2[(size_t)e2.x * 32 + lane];
        float2 r3 = in2[(size_t)e3.x * 32 + lane];
        float w0 = __int_as_float(e0.y), w1 = __int_as_float(e1.y);
        float w2 = __int_as_float(e2.y), w3 = __int_as_float(e3.y);
        a0.x = fmaf(w0, r0.x, a0.x); a0.y = fmaf(w0, r0.y, a0.y);
        a1.x = fmaf(w1, r1.x, a1.x); a1.y = fmaf(w1, r1.y, a1.y);
        a2.x = fmaf(w2, r2.x, a2.x); a2.y = fmaf(w2, r2.y, a2.y);
        a3.x = fmaf(w3, r3.x, a3.x); a3.y = fmaf(w3, r3.y, a3.y);
    }
    for (; j < end; j++) {
        int2 e0 = __ldg(&g_cse[j]);
        float w0 = __int_as_float(e0.y);
        float2 r0 = in2[(size_t)e0.x * 32 + lane];
        a0.x = fmaf(w0, r0.x, a0.x); a0.y = fmaf(w0, r0.y, a0.y);
    }
    float2 s;
    s.x = (a0.x + a1.x) + (a2.x + a3.x);
    s.y = (a0.y + a1.y) + (a2.y + a3.y);
    float2* ou = phase ? (float2*)g_tx2 : (float2*)g_tx1;
    ou[(size_t)node * 32 + lane] = s;
}

// tensor-core Cheb GEMM -> H (fp16) + attention dots via vs/vd.
// 128 nodes per 256-thread block (8 warps x 16 rows).
__global__ void __launch_bounds__(256) k_mma1(const float* __restrict__ cb, int n) {
    __shared__ __align__(16) char sbuf[40960];
    __shared__ float s_cb[64];
    __shared__ float s_vs[256], s_vd[256];
    __half* sA     = (__half*)sbuf;              // [128][104]
    unsigned* sW1u = (unsigned*)(sbuf + 26624);  // [64][52] uints

    int t = threadIdx.x;
    int base = blockIdx.x * 128;
    int lane = t & 31, w = t >> 5;
    int g = lane >> 2, tt = lane & 3;

    if (t < 64) s_cb[t] = cb[t];
    s_vs[t] = g_vs[t];
    s_vd[t] = g_vd[t];

    float acc1[8][4];
    #pragma unroll
    for (int i = 0; i < 8; i++)
        #pragma unroll
        for (int q = 0; q < 4; q++) acc1[i][q] = 0.f;

    #pragma unroll
    for (int kh = 0; kh < 2; kh++) {
        __syncthreads();
        #pragma unroll
        for (int i = 0; i < 16; i++) {
            int idx = t + 256 * i;
            int m = idx >> 5, cl = idx & 31;
            int c = (kh << 5) + cl;
            int node = base + m;
            float t0 = 0.f, t1 = 0.f, t2 = 0.f;
            if (node < n) {
                t0 = g_xln[node * 64 + c];
                t1 = g_tx1[node * 64 + c];
                t2 = 2.f * g_tx2[node * 64 + c] - t0;
            }
            __half* p = sA + m * 104 + 3 * cl;
            p[0] = __float2half(t0);
            p[1] = __float2half(t1);
            p[2] = __float2half(t2);
        }
        const unsigned* wct = (const unsigned*)g_wct;   // [64][96] uints
        #pragma unroll
        for (int i = 0; i < 12; i++) {
            int idx = t + 256 * i;
            int nn = idx / 48, c2 = idx % 48;
            sW1u[nn * 52 + c2] = wct[nn * 96 + 48 * kh + c2];
        }
        __syncthreads();
        const unsigned* Au = (const unsigned*)sA;       // [128][52]
        #pragma unroll
        for (int ks = 0; ks < 6; ks++) {
            int arow = 16 * w + g;
            unsigned a0 = Au[arow * 52 + 8 * ks + tt];
            unsigned a1 = Au[(arow + 8) * 52 + 8 * ks + tt];
            unsigned a2 = Au[arow * 52 + 8 * ks + tt + 4];
            unsigned a3 = Au[(arow + 8) * 52 + 8 * ks + tt + 4];
            #pragma unroll
            for (int ns = 0; ns < 8; ns++) {
                int nc = 8 * ns + g;
                unsigned b0 = sW1u[nc * 52 + 8 * ks + tt];
                unsigned b1 = sW1u[nc * 52 + 8 * ks + tt + 4];
                mma16816(acc1[ns], a0, a1, a2, a3, b0, b1);
            }
        }
    }

    // epilogue: bias + leaky -> H fp16; attention dots vs/vd (fp32)
    int node0 = base + 16 * w + g, node1 = node0 + 8;
    float sv0[NH] = {0,0,0,0}, dv0[NH] = {0,0,0,0};
    float sv1[NH] = {0,0,0,0}, dv1[NH] = {0,0,0,0};
    #pragma unroll
    for (int ns = 0; ns < 8; ns++) {
        int col = 8 * ns + 2 * tt;
        float b0f = s_cb[col], b1f = s_cb[col + 1];
        float h0 = leaky(acc1[ns][0] + b0f, 0.01f);
        float h1 = leaky(acc1[ns][1] + b1f, 0.01f);
        float h2 = leaky(acc1[ns][2] + b0f, 0.01f);
        float h3 = leaky(acc1[ns][3] + b1f, 0.01f);
        if (node0 < n) {
            __half2 hv = __floats2half2_rn(h0, h1);
            g_h16[(size_t)node0 * 32 + (col >> 1)] = *(unsigned*)&hv;
        }
        if (node1 < n) {
            __half2 hv = __floats2half2_rn(h2, h3);
            g_h16[(size_t)node1 * 32 + (col >> 1)] = *(unsigned*)&hv;
        }
        #pragma unroll
        for (int h = 0; h < NH; h++) {
            float vsa = s_vs[h * 64 + col], vsb = s_vs[h * 64 + col + 1];
            float vda = s_vd[h * 64 + col], vdb = s_vd[h * 64 + col + 1];
            sv0[h] = fmaf(h0, vsa, fmaf(h1, vsb, sv0[h]));
            dv0[h] = fmaf(h0, vda, fmaf(h1, vdb, dv0[h]));
            sv1[h] = fmaf(h2, vsa, fmaf(h3, vsb, sv1[h]));
            dv1[h] = fmaf(h2, vda, fmaf(h3, vdb, dv1[h]));
        }
    }
    #pragma unroll
    for (int o = 1; o <= 2; o <<= 1)
        #pragma unroll
        for (int h = 0; h < NH; h++) {
            sv0[h] += __shfl_xor_sync(0xffffffffu, sv0[h], o);
            dv0[h] += __shfl_xor_sync(0xffffffffu, dv0[h], o);
            sv1[h] += __shfl_xor_sync(0xffffffffu, sv1[h], o);
            dv1[h] += __shfl_xor_sync(0xffffffffu, dv1[h], o);
        }
    if (tt == 0) {
        #pragma unroll
        for (int h = 0; h < NH; h++) {
            if (node0 < n) { g_asrc[node0 * 4 + h] = sv0[h]; g_adst[node0 * 4 + h] = dv0[h]; }
            if (node1 < n) { g_asrc[node1 * 4 + h] = sv1[h]; g_adst[node1 * 4 + h] = dv1[h]; }
        }
    }
}

// fused GAT aggregation in H-space: softmax + per-head weighted sums of H.
// warp per node; lane owns features (2*lane, 2*lane+1); 4B load/edge/lane.
__global__ void k_gat(int n) {
    __shared__ float4 s_ex[8][32];
    __shared__ int    s_s[8][32];
    int wid = threadIdx.x >> 5;
    int node = (blockIdx.x * blockDim.x + threadIdx.x) >> 5;
    int lane = threadIdx.x & 31;
    if (node >= n) return;
    int beg = g_rowptr[node], end = g_rowptr[node + 1];

    const float4* pa = reinterpret_cast<const float4*>(g_asrc);
    const float4* pd = reinterpret_cast<const float4*>(g_adst);
    float4 adv = pd[node];
    float4 asn = pa[node];
    float selfex[NH];
    selfex[0] = __expf(leaky(asn.x + adv.x, 0.2f));
    selfex[1] = __expf(leaky(asn.y + adv.y, 0.2f));
    selfex[2] = __expf(leaky(asn.z + adv.z, 0.2f));
    selfex[3] = __expf(leaky(asn.w + adv.w, 0.2f));

    float2 m[NH];
    {
        unsigned u = g_h16[(size_t)node * 32 + lane];
        float2 f = __half22float2(*(__half2*)&u);
        #pragma unroll
        for (int h = 0; h < NH; h++)
            m[h] = make_float2(selfex[h] * f.x, selfex[h] * f.y);
    }
    float den[NH] = {0.f, 0.f, 0.f, 0.f};

    for (int j0 = beg; j0 < end; j0 += 32) {
        int cnt = min(32, end - j0);
        float4 ex = make_float4(0.f, 0.f, 0.f, 0.f);
        int s = 0;
        if (lane < cnt) {
            s = __ldg(&g_cse[j0 + lane]).x;
            float4 av = pa[s];
            ex.x = __expf(leaky(av.x + adv.x, 0.2f));
            ex.y = __expf(leaky(av.y + adv.y, 0.2f));
            ex.z = __expf(leaky(av.z + adv.z, 0.2f));
            ex.w = __expf(leaky(av.w + adv.w, 0.2f));
            den[0] += ex.x; den[1] += ex.y; den[2] += ex.z; den[3] += ex.w;
        }
        s_ex[wid][lane] = ex;
        s_s[wid][lane] = s;
        __syncwarp();
        #pragma unroll 4
        for (int k = 0; k < cnt; k++) {
            int sk = s_s[wid][k];
            float4 exk = s_ex[wid][k];
            unsigned u = __ldg(&g_h16[(size_t)sk * 32 + lane]);
            float2 f = __half22float2(*(__half2*)&u);
            m[0].x = fmaf(exk.x, f.x, m[0].x); m[0].y = fmaf(exk.x, f.y, m[0].y);
            m[1].x = fmaf(exk.y, f.x, m[1].x); m[1].y = fmaf(exk.y, f.y, m[1].y);
            m[2].x = fmaf(exk.z, f.x, m[2].x); m[2].y = fmaf(exk.z, f.y, m[2].y);
            m[3].x = fmaf(exk.w, f.x, m[3].x); m[3].y = fmaf(exk.w, f.y, m[3].y);
        }
        __syncwarp();
    }

    #pragma unroll
    for (int o = 16; o; o >>= 1)
        #pragma unroll
        for (int h = 0; h < NH; h++)
            den[h] += __shfl_xor_sync(0xffffffffu, den[h], o);

    #pragma unroll
    for (int h = 0; h < NH; h++) {
        float iv = 1.f / (den[h] + selfex[h] + 1e-16f);
        __half2 hv = __floats2half2_rn(m[h].x * iv, m[h].y * iv);
        g_M16[(size_t)node * 128 + h * 32 + lane] = *(unsigned*)&hv;
    }
}

// tensor-core final GEMM: out = leaky(M @ Wg2 + gb). 128 nodes/block.
__global__ void __launch_bounds__(256) k_mma2(const float* __restrict__ gb,
                                              float* __restrict__ out, int n) {
    __shared__ __align__(16) unsigned sB[64 * 132];   // Wg2 [64 n][128+4 k-uints]
    __shared__ float s_gb[64];
    int t = threadIdx.x;
    int lane = t & 31, w = t >> 5;
    int g = lane >> 2, tt = lane & 3;

    const unsigned* wg2u = (const unsigned*)g_wg2;    // [64][128]
    for (int i = t; i < 64 * 128; i += 256) {
        int nc = i >> 7, c2 = i & 127;
        sB[nc * 132 + c2] = wg2u[i];
    }
    if (t < 64) s_gb[t] = gb[t];
    __syncthreads();

    int base = blockIdx.x * 128;
    int arow = 16 * w + g;
    int node0 = base + arow, node1 = node0 + 8;

    float acc[8][4];
    #pragma unroll
    for (int i = 0; i < 8; i++)
        #pragma unroll
        for (int q = 0; q < 4; q++) acc[i][q] = 0.f;

    #pragma unroll
    for (int ks = 0; ks < 16; ks++) {
        unsigned a0 = __ldg(&g_M16[(size_t)node0 * 128 + 8 * ks + tt]);
        unsigned a1 = __ldg(&g_M16[(size_t)node1 * 128 + 8 * ks + tt]);
        unsigned a2 = __ldg(&g_M16[(size_t)node0 * 128 + 8 * ks + tt + 4]);
        unsigned a3 = __ldg(&g_M16[(size_t)node1 * 128 + 8 * ks + tt + 4]);
        #pragma unroll
        for (int ns = 0; ns < 8; ns++) {
            int nc = 8 * ns + g;
            unsigned b0 = sB[nc * 132 + 8 * ks + tt];
            unsigned b1 = sB[nc * 132 + 8 * ks + tt + 4];
            mma16816(acc[ns], a0, a1, a2, a3, b0, b1);
        }
    }

    #pragma unroll
    for (int ns = 0; ns < 8; ns++) {
        int col = 8 * ns + 2 * tt;
        float b0f = s_gb[col], b1f = s_gb[col + 1];
        if (node0 < n) {
            float2 v = make_float2(leaky(acc[ns][0] + b0f, 0.01f),
                                   leaky(acc[ns][1] + b1f, 0.01f));
            *reinterpret_cast<float2*>(out + (size_t)node0 * 64 + col) = v;
        }
        if (node1 < n) {
            float2 v = make_float2(leaky(acc[ns][2] + b0f, 0.01f),
                                   leaky(acc[ns][3] + b1f, 0.01f));
            *reinterpret_cast<float2*>(out + (size_t)node1 * 64 + col) = v;
        }
    }
}

// ---------------- launch ----------------
extern "C" void kernel_launch(void* const* d_in, const int* in_sizes, int n_in,
                              void* d_out, int out_size) {
    const float* x      = (const float*)d_in[0];
    const int*   ei     = (const int*)  d_in[1];
    const float* ea     = (const float*)d_in[2];
    const float* lng    = (const float*)d_in[3];
    const float* lnb    = (const float*)d_in[4];
    const float* cw     = (const float*)d_in[5];
    const float* cb     = (const float*)d_in[6];
    const float* gw     = (const float*)d_in[7];
    const float* as     = (const float*)d_in[8];
    const float* ad     = (const float*)d_in[9];
    const float* gb     = (const float*)d_in[10];
    float* out = (float*)d_out;

    const int n = in_sizes[0] / F;        // 50000
    const int e = in_sizes[2];            // 800000
    const int* src = ei;
    const int* dst = ei + e;

    const int TB = 256;
    auto cdiv = [](long long a, long long b) { return (int)((a + b - 1) / b); };
    int nb = cdiv(n, 256);

    k_init  <<<cdiv(n, TB), TB>>>(n);
    k_prep  <<<cdiv(64 * 192 + 64 * 256 + 512, TB), TB>>>(cw, gw, as, ad);
    k_ln    <<<cdiv((long long)n * 32, TB), TB>>>(x, lng, lnb, n);
    k_degcnt<<<cdiv(e, TB), TB>>>(src, dst, ea, e);
    k_scan1 <<<nb, 256>>>(n);
    k_scan2 <<<1, 256>>>(nb);
    k_scan3 <<<cdiv(n, TB), TB>>>(n, e);
    k_fill  <<<cdiv(e, TB), TB>>>(src, dst, ea, e);
    k_prop  <<<cdiv((long long)n * 32, TB), TB>>>(n, 0);
    k_prop  <<<cdiv((long long)n * 32, TB), TB>>>(n, 1);
    k_mma1  <<<cdiv(n, 128), 256>>>(cb, n);
    k_gat   <<<cdiv((long long)n * 32, TB), TB>>>(n);
    k_mma2  <<<cdiv(n, 128), 256>>>(gb, out, n);
}

// round 12
// speedup vs baseline: 1.6533x; 1.0915x over previous
#include <cuda_runtime.h>
#include <cuda_fp16.h>
#include <math.h>

#define NMAX 50000
#define NPAD 50176
#define EMAX 800000
#define F 64
#define NH 4

// ---------------- scratch (device globals; referenced ONLY from device code) ----------------
__device__ unsigned g_x16[(size_t)NMAX * 32];    // Tx0 fp16, [node][feat/2]
__device__ unsigned g_t116[(size_t)NMAX * 32];   // Tx1 fp16
__device__ unsigned g_t216[(size_t)NMAX * 32];   // Tx2 fp16
__device__ unsigned g_h16[(size_t)NPAD * 32];    // H fp16 (128B rows)
__device__ unsigned g_M16[(size_t)NPAD * 128];   // M fp16, [node][head*32 + feat/2]
__device__ float    g_asrc[NMAX * NH];
__device__ float    g_adst[NMAX * NH];
__device__ float    g_deg[NMAX];
__device__ float    g_dinv[NMAX];
__device__ int      g_cnt[NMAX];
__device__ int      g_loc[NMAX];
__device__ int      g_bsum[256];
__device__ int      g_rowptr[NMAX + 1];
__device__ int      g_cursor[NMAX];
__device__ int2     g_cse[EMAX];                 // CSR: (src, weight-as-int)
__device__ __half   g_wct[64 * 192];             // Cheb weights, transposed [n][3c+j]
__device__ __half   g_wg2[64 * 256];             // 0.25*stacked Wg, [n_out][h*64+c]
__device__ float    g_vs[NH * 64];               // Wg_h^T att_src_h
__device__ float    g_vd[NH * 64];               // Wg_h^T att_dst_h

__device__ __forceinline__ float leaky(float x, float s) {
    return x >= 0.f ? x : s * x;
}

__device__ __forceinline__ void mma16816(float* c, unsigned a0, unsigned a1,
                                         unsigned a2, unsigned a3,
                                         unsigned b0, unsigned b1) {
    asm volatile(
        "mma.sync.aligned.m16n8k16.row.col.f32.f16.f16.f32 "
        "{%0,%1,%2,%3}, {%4,%5,%6,%7}, {%8,%9}, {%0,%1,%2,%3};\n"
        : "+f"(c[0]), "+f"(c[1]), "+f"(c[2]), "+f"(c[3])
        : "r"(a0), "r"(a1), "r"(a2), "r"(a3), "r"(b0), "r"(b1));
}

// ---------------- kernels ----------------
// init counters + one-time weight prep, single launch
__global__ void k_setup(const float* __restrict__ cw, const float* __restrict__ gw,
                        const float* __restrict__ as, const float* __restrict__ ad,
                        int n) {
    int i = blockIdx.x * blockDim.x + threadIdx.x;
    if (i < n) { g_deg[i] = 0.f; g_cnt[i] = 0; }
    if (i < 64 * 192) {
        int nn = i / 192, k = i % 192;
        int c = k / 3, j = k % 3;
        g_wct[i] = __float2half(cw[j * 4096 + c * 64 + nn]);
    } else if (i < 64 * 192 + 64 * 256) {
        int q = i - 64 * 192;
        int nn = q >> 8, k = q & 255;
        int h = k >> 6, c = k & 63;
        g_wg2[q] = __float2half(0.25f * gw[c * 256 + h * 64 + nn]);
    } else if (i < 64 * 192 + 64 * 256 + 512) {
        int q = i - 64 * 192 - 64 * 256;
        int isd = q >> 8, h = (q >> 6) & 3, c = q & 63;
        const float* av = isd ? ad : as;
        float acc = 0.f;
        for (int f = 0; f < 64; f++)
            acc = fmaf(gw[c * 256 + h * 64 + f], av[h * 64 + f], acc);
        if (isd) g_vd[h * 64 + c] = acc; else g_vs[h * 64 + c] = acc;
    }
}

// layernorm (warp/node, lane owns feats 2l,2l+1 -> half2) + degree/count atomics
__global__ void k_lndeg(const float* __restrict__ x, const float* __restrict__ gamma,
                        const float* __restrict__ beta,
                        const int* __restrict__ src, const int* __restrict__ dst,
                        const float* __restrict__ ea, int n, int e, int lnBlocks) {
    if ((int)blockIdx.x < lnBlocks) {
        int warp = (blockIdx.x * blockDim.x + threadIdx.x) >> 5;
        int lane = threadIdx.x & 31;
        if (warp >= n) return;
        float2 v = reinterpret_cast<const float2*>(x)[(size_t)warp * 32 + lane];
        float s = v.x + v.y, sq = v.x * v.x + v.y * v.y;
        #pragma unroll
        for (int o = 16; o; o >>= 1) {
            s  += __shfl_xor_sync(0xffffffffu, s,  o);
            sq += __shfl_xor_sync(0xffffffffu, sq, o);
        }
        float mu  = s * (1.f / 64.f);
        float var = sq * (1.f / 64.f) - mu * mu;
        float r = rsqrtf(var + 1e-5f);
        float2 g2 = reinterpret_cast<const float2*>(gamma)[lane];
        float2 b2 = reinterpret_cast<const float2*>(beta)[lane];
        __half2 h = __floats2half2_rn((v.x - mu) * r * g2.x + b2.x,
                                      (v.y - mu) * r * g2.y + b2.y);
        g_x16[(size_t)warp * 32 + lane] = *(unsigned*)&h;
    } else {
        int i = (blockIdx.x - lnBlocks) * blockDim.x + threadIdx.x;
        if (i >= e) return;
        atomicAdd(&g_deg[src[i]], ea[i]);
        atomicAdd(&g_cnt[dst[i]], 1);
    }
}

// ---- 3-phase parallel exclusive scan of g_cnt ----
__global__ void k_scan1(int n) {
    __shared__ int sm[256];
    int t = threadIdx.x;
    int i = blockIdx.x * 256 + t;
    int v = (i < n) ? g_cnt[i] : 0;
    sm[t] = v;
    __syncthreads();
    for (int o = 1; o < 256; o <<= 1) {
        int u = (t >= o) ? sm[t - o] : 0;
        __syncthreads();
        sm[t] += u;
        __syncthreads();
    }
    if (i < n) g_loc[i] = sm[t] - v;
    if (t == 255) g_bsum[blockIdx.x] = sm[255];
}

__global__ void k_scan2(int nb) {
    __shared__ int sm[256];
    int t = threadIdx.x;
    int v = (t < nb) ? g_bsum[t] : 0;
    sm[t] = v;
    __syncthreads();
    for (int o = 1; o < 256; o <<= 1) {
        int u = (t >= o) ? sm[t - o] : 0;
        __syncthreads();
        sm[t] += u;
        __syncthreads();
    }
    if (t < nb) g_bsum[t] = sm[t] - v;
}

__global__ void k_scan3(int n, int e) {
    int i = blockIdx.x * blockDim.x + threadIdx.x;
    if (i < n) {
        int r = g_bsum[i >> 8] + g_loc[i];
        g_rowptr[i] = r;
        g_cursor[i] = r;
        float d = g_deg[i];
        g_dinv[i] = d > 0.f ? rsqrtf(d) : 0.f;
    }
    if (i == 0) g_rowptr[n] = e;
}

__global__ void k_fill(const int* __restrict__ src, const int* __restrict__ dst,
                       const float* __restrict__ ea, int e) {
    int i = blockIdx.x * blockDim.x + threadIdx.x;
    if (i >= e) return;
    int s = src[i], d = dst[i];
    int pos = atomicAdd(&g_cursor[d], 1);
    float w = -(g_dinv[s] * ea[i] * g_dinv[d]);
    g_cse[pos] = make_int2(s, __float_as_int(w));
}

// fp16 gather propagation; warp per node; half2 per lane; 4-edge ILP; fp32 accum
__global__ void k_prop(int n, int phase) {
    int node = (blockIdx.x * blockDim.x + threadIdx.x) >> 5;
    int lane = threadIdx.x & 31;
    if (node >= n) return;
    const unsigned* in = phase ? g_t116 : g_x16;
    int beg = g_rowptr[node], end = g_rowptr[node + 1];
    float2 a0 = {0.f, 0.f}, a1 = {0.f, 0.f}, a2 = {0.f, 0.f}, a3 = {0.f, 0.f};
    int j = beg;
    for (; j + 4 <= end; j += 4) {
        int2 e0 = __ldg(&g_cse[j]),     e1 = __ldg(&g_cse[j + 1]);
        int2 e2 = __ldg(&g_cse[j + 2]), e3 = __ldg(&g_cse[j + 3]);
        unsigned u0 = in[(size_t)e0.x * 32 + lane];
        unsigned u1 = in[(size_t)e1.x * 32 + lane];
        unsigned u2 = in[(size_t)e2.x * 32 + lane];
        unsigned u3 = in[(size_t)e3.x * 32 + lane];
        float2 r0 = __half22float2(*(__half2*)&u0);
        float2 r1 = __half22float2(*(__half2*)&u1);
        float2 r2 = __half22float2(*(__half2*)&u2);
        float2 r3 = __half22float2(*(__half2*)&u3);
        float w0 = __int_as_float(e0.y), w1 = __int_as_float(e1.y);
        float w2 = __int_as_float(e2.y), w3 = __int_as_float(e3.y);
        a0.x = fmaf(w0, r0.x, a0.x); a0.y = fmaf(w0, r0.y, a0.y);
        a1.x = fmaf(w1, r1.x, a1.x); a1.y = fmaf(w1, r1.y, a1.y);
        a2.x = fmaf(w2, r2.x, a2.x); a2.y = fmaf(w2, r2.y, a2.y);
        a3.x = fmaf(w3, r3.x, a3.x); a3.y = fmaf(w3, r3.y, a3.y);
    }
    for (; j < end; j++) {
        int2 e0 = __ldg(&g_cse[j]);
        float w0 = __int_as_float(e0.y);
        unsigned u0 = in[(size_t)e0.x * 32 + lane];
        float2 r0 = __half22float2(*(__half2*)&u0);
        a0.x = fmaf(w0, r0.x, a0.x); a0.y = fmaf(w0, r0.y, a0.y);
    }
    __half2 h = __floats2half2_rn((a0.x + a1.x) + (a2.x + a3.x),
                                  (a0.y + a1.y) + (a2.y + a3.y));
    unsigned* ou = phase ? g_t216 : g_t116;
    ou[(size_t)node * 32 + lane] = *(unsigned*)&h;
}

// tensor-core Cheb GEMM -> H (fp16) + attention dots via vs/vd.
// 128 nodes per 256-thread block (8 warps x 16 rows).
__global__ void __launch_bounds__(256) k_mma1(const float* __restrict__ cb, int n) {
    __shared__ __align__(16) char sbuf[40960];
    __shared__ float s_cb[64];
    __shared__ float s_vs[256], s_vd[256];
    __half* sA     = (__half*)sbuf;              // [128][104]
    unsigned* sW1u = (unsigned*)(sbuf + 26624);  // [64][52] uints

    int t = threadIdx.x;
    int base = blockIdx.x * 128;
    int lane = t & 31, w = t >> 5;
    int g = lane >> 2, tt = lane & 3;

    if (t < 64) s_cb[t] = cb[t];
    s_vs[t] = g_vs[t];
    s_vd[t] = g_vd[t];

    float acc1[8][4];
    #pragma unroll
    for (int i = 0; i < 8; i++)
        #pragma unroll
        for (int q = 0; q < 4; q++) acc1[i][q] = 0.f;

    #pragma unroll
    for (int kh = 0; kh < 2; kh++) {
        __syncthreads();
        // stage A from fp16 buffers: thread -> (node m, uint-pair ul in 0..15)
        #pragma unroll
        for (int i = 0; i < 8; i++) {
            int idx = t + 256 * i;             // 0..2047
            int m = idx >> 4, ul = idx & 15;
            int node = base + m;
            unsigned u0 = 0, u1 = 0, u2 = 0;
            if (node < n) {
                size_t off = (size_t)node * 32 + 16 * kh + ul;
                u0 = g_x16[off];
                u1 = g_t116[off];
                u2 = g_t216[off];
            }
            float2 f0 = __half22float2(*(__half2*)&u0);
            float2 f1 = __half22float2(*(__half2*)&u1);
            float2 f2 = __half22float2(*(__half2*)&u2);
            float t2lo = 2.f * f2.x - f0.x, t2hi = 2.f * f2.y - f0.y;
            __half2 p0 = __floats2half2_rn(f0.x, f1.x);
            __half2 p1 = __floats2half2_rn(t2lo, f0.y);
            __half2 p2 = __floats2half2_rn(f1.y, t2hi);
            unsigned* dp = (unsigned*)sA + m * 52 + 3 * ul;
            dp[0] = *(unsigned*)&p0;
            dp[1] = *(unsigned*)&p1;
            dp[2] = *(unsigned*)&p2;
        }
        const unsigned* wct = (const unsigned*)g_wct;   // [64][96] uints
        #pragma unroll
        for (int i = 0; i < 12; i++) {
            int idx = t + 256 * i;
            int nn = idx / 48, c2 = idx % 48;
            sW1u[nn * 52 + c2] = wct[nn * 96 + 48 * kh + c2];
        }
        __syncthreads();
        const unsigned* Au = (const unsigned*)sA;       // [128][52]
        #pragma unroll
        for (int ks = 0; ks < 6; ks++) {
            int arow = 16 * w + g;
            unsigned a0 = Au[arow * 52 + 8 * ks + tt];
            unsigned a1 = Au[(arow + 8) * 52 + 8 * ks + tt];
            unsigned a2 = Au[arow * 52 + 8 * ks + tt + 4];
            unsigned a3 = Au[(arow + 8) * 52 + 8 * ks + tt + 4];
            #pragma unroll
            for (int ns = 0; ns < 8; ns++) {
                int nc = 8 * ns + g;
                unsigned b0 = sW1u[nc * 52 + 8 * ks + tt];
                unsigned b1 = sW1u[nc * 52 + 8 * ks + tt + 4];
                mma16816(acc1[ns], a0, a1, a2, a3, b0, b1);
            }
        }
    }

    // epilogue: bias + leaky -> H fp16; attention dots vs/vd (fp32)
    int node0 = base + 16 * w + g, node1 = node0 + 8;
    float sv0[NH] = {0,0,0,0}, dv0[NH] = {0,0,0,0};
    float sv1[NH] = {0,0,0,0}, dv1[NH] = {0,0,0,0};
    #pragma unroll
    for (int ns = 0; ns < 8; ns++) {
        int col = 8 * ns + 2 * tt;
        float b0f = s_cb[col], b1f = s_cb[col + 1];
        float h0 = leaky(acc1[ns][0] + b0f, 0.01f);
        float h1 = leaky(acc1[ns][1] + b1f, 0.01f);
        float h2 = leaky(acc1[ns][2] + b0f, 0.01f);
        float h3 = leaky(acc1[ns][3] + b1f, 0.01f);
        if (node0 < n) {
            __half2 hv = __floats2half2_rn(h0, h1);
            g_h16[(size_t)node0 * 32 + (col >> 1)] = *(unsigned*)&hv;
        }
        if (node1 < n) {
            __half2 hv = __floats2half2_rn(h2, h3);
            g_h16[(size_t)node1 * 32 + (col >> 1)] = *(unsigned*)&hv;
        }
        #pragma unroll
        for (int h = 0; h < NH; h++) {
            float vsa = s_vs[h * 64 + col], vsb = s_vs[h * 64 + col + 1];
            float vda = s_vd[h * 64 + col], vdb = s_vd[h * 64 + col + 1];
            sv0[h] = fmaf(h0, vsa, fmaf(h1, vsb, sv0[h]));
            dv0[h] = fmaf(h0, vda, fmaf(h1, vdb, dv0[h]));
            sv1[h] = fmaf(h2, vsa, fmaf(h3, vsb, sv1[h]));
            dv1[h] = fmaf(h2, vda, fmaf(h3, vdb, dv1[h]));
        }
    }
    #pragma unroll
    for (int o = 1; o <= 2; o <<= 1)
        #pragma unroll
        for (int h = 0; h < NH; h++) {
            sv0[h] += __shfl_xor_sync(0xffffffffu, sv0[h], o);
            dv0[h] += __shfl_xor_sync(0xffffffffu, dv0[h], o);
            sv1[h] += __shfl_xor_sync(0xffffffffu, sv1[h], o);
            dv1[h] += __shfl_xor_sync(0xffffffffu, dv1[h], o);
        }
    if (tt == 0) {
        #pragma unroll
        for (int h = 0; h < NH; h++) {
            if (node0 < n) { g_asrc[node0 * 4 + h] = sv0[h]; g_adst[node0 * 4 + h] = dv0[h]; }
            if (node1 < n) { g_asrc[node1 * 4 + h] = sv1[h]; g_adst[node1 * 4 + h] = dv1[h]; }
        }
    }
}

// fused GAT aggregation in H-space: softmax + per-head weighted sums of H.
// warp per node; lane owns features (2*lane, 2*lane+1); 4B load/edge/lane.
__global__ void k_gat(int n) {
    __shared__ float4 s_ex[8][32];
    __shared__ int    s_s[8][32];
    int wid = threadIdx.x >> 5;
    int node = (blockIdx.x * blockDim.x + threadIdx.x) >> 5;
    int lane = threadIdx.x & 31;
    if (node >= n) return;
    int beg = g_rowptr[node], end = g_rowptr[node + 1];

    const float4* pa = reinterpret_cast<const float4*>(g_asrc);
    const float4* pd = reinterpret_cast<const float4*>(g_adst);
    float4 adv = pd[node];
    float4 asn = pa[node];
    float selfex[NH];
    selfex[0] = __expf(leaky(asn.x + adv.x, 0.2f));
    selfex[1] = __expf(leaky(asn.y + adv.y, 0.2f));
    selfex[2] = __expf(leaky(asn.z + adv.z, 0.2f));
    selfex[3] = __expf(leaky(asn.w + adv.w, 0.2f));

    float2 m[NH];
    {
        unsigned u = g_h16[(size_t)node * 32 + lane];
        float2 f = __half22float2(*(__half2*)&u);
        #pragma unroll
        for (int h = 0; h < NH; h++)
            m[h] = make_float2(selfex[h] * f.x, selfex[h] * f.y);
    }
    float den[NH] = {0.f, 0.f, 0.f, 0.f};

    for (int j0 = beg; j0 < end; j0 += 32) {
        int cnt = min(32, end - j0);
        float4 ex = make_float4(0.f, 0.f, 0.f, 0.f);
        int s = 0;
        if (lane < cnt) {
            s = __ldg(&g_cse[j0 + lane]).x;
            float4 av = pa[s];
            ex.x = __expf(leaky(av.x + adv.x, 0.2f));
            ex.y = __expf(leaky(av.y + adv.y, 0.2f));
            ex.z = __expf(leaky(av.z + adv.z, 0.2f));
            ex.w = __expf(leaky(av.w + adv.w, 0.2f));
            den[0] += ex.x; den[1] += ex.y; den[2] += ex.z; den[3] += ex.w;
        }
        s_ex[wid][lane] = ex;
        s_s[wid][lane] = s;
        __syncwarp();
        #pragma unroll 4
        for (int k = 0; k < cnt; k++) {
            int sk = s_s[wid][k];
            float4 exk = s_ex[wid][k];
            unsigned u = __ldg(&g_h16[(size_t)sk * 32 + lane]);
            float2 f = __half22float2(*(__half2*)&u);
            m[0].x = fmaf(exk.x, f.x, m[0].x); m[0].y = fmaf(exk.x, f.y, m[0].y);
            m[1].x = fmaf(exk.y, f.x, m[1].x); m[1].y = fmaf(exk.y, f.y, m[1].y);
            m[2].x = fmaf(exk.z, f.x, m[2].x); m[2].y = fmaf(exk.z, f.y, m[2].y);
            m[3].x = fmaf(exk.w, f.x, m[3].x); m[3].y = fmaf(exk.w, f.y, m[3].y);
        }
        __syncwarp();
    }

    #pragma unroll
    for (int o = 16; o; o >>= 1)
        #pragma unroll
        for (int h = 0; h < NH; h++)
            den[h] += __shfl_xor_sync(0xffffffffu, den[h], o);

    #pragma unroll
    for (int h = 0; h < NH; h++) {
        float iv = 1.f / (den[h] + selfex[h] + 1e-16f);
        __half2 hv = __floats2half2_rn(m[h].x * iv, m[h].y * iv);
        g_M16[(size_t)node * 128 + h * 32 + lane] = *(unsigned*)&hv;
    }
}

// tensor-core final GEMM: out = leaky(M @ Wg2 + gb). 128 nodes/block.
__global__ void __launch_bounds__(256) k_mma2(const float* __restrict__ gb,
                                              float* __restrict__ out, int n) {
    __shared__ __align__(16) unsigned sB[64 * 132];
    __shared__ float s_gb[64];
    int t = threadIdx.x;
    int lane = t & 31, w = t >> 5;
    int g = lane >> 2, tt = lane & 3;

    const unsigned* wg2u = (const unsigned*)g_wg2;    // [64][128]
    for (int i = t; i < 64 * 128; i += 256) {
        int nc = i >> 7, c2 = i & 127;
        sB[nc * 132 + c2] = wg2u[i];
    }
    if (t < 64) s_gb[t] = gb[t];
    __syncthreads();

    int base = blockIdx.x * 128;
    int arow = 16 * w + g;
    int node0 = base + arow, node1 = node0 + 8;

    float acc[8][4];
    #pragma unroll
    for (int i = 0; i < 8; i++)
        #pragma unroll
        for (int q = 0; q < 4; q++) acc[i][q] = 0.f;

    #pragma unroll
    for (int ks = 0; ks < 16; ks++) {
        unsigned a0 = __ldg(&g_M16[(size_t)node0 * 128 + 8 * ks + tt]);
        unsigned a1 = __ldg(&g_M16[(size_t)node1 * 128 + 8 * ks + tt]);
        unsigned a2 = __ldg(&g_M16[(size_t)node0 * 128 + 8 * ks + tt + 4]);
        unsigned a3 = __ldg(&g_M16[(size_t)node1 * 128 + 8 * ks + tt + 4]);
        #pragma unroll
        for (int ns = 0; ns < 8; ns++) {
            int nc = 8 * ns + g;
            unsigned b0 = sB[nc * 132 + 8 * ks + tt];
            unsigned b1 = sB[nc * 132 + 8 * ks + tt + 4];
            mma16816(acc[ns], a0, a1, a2, a3, b0, b1);
        }
    }

    #pragma unroll
    for (int ns = 0; ns < 8; ns++) {
        int col = 8 * ns + 2 * tt;
        float b0f = s_gb[col], b1f = s_gb[col + 1];
        if (node0 < n) {
            float2 v = make_float2(leaky(acc[ns][0] + b0f, 0.01f),
                                   leaky(acc[ns][1] + b1f, 0.01f));
            *reinterpret_cast<float2*>(out + (size_t)node0 * 64 + col) = v;
        }
        if (node1 < n) {
            float2 v = make_float2(leaky(acc[ns][2] + b0f, 0.01f),
                                   leaky(acc[ns][3] + b1f, 0.01f));
            *reinterpret_cast<float2*>(out + (size_t)node1 * 64 + col) = v;
        }
    }
}

// ---------------- launch ----------------
extern "C" void kernel_launch(void* const* d_in, const int* in_sizes, int n_in,
                              void* d_out, int out_size) {
    const float* x      = (const float*)d_in[0];
    const int*   ei     = (const int*)  d_in[1];
    const float* ea     = (const float*)d_in[2];
    const float* lng    = (const float*)d_in[3];
    const float* lnb    = (const float*)d_in[4];
    const float* cw     = (const float*)d_in[5];
    const float* cb     = (const float*)d_in[6];
    const float* gw     = (const float*)d_in[7];
    const float* as     = (const float*)d_in[8];
    const float* ad     = (const float*)d_in[9];
    const float* gb     = (const float*)d_in[10];
    float* out = (float*)d_out;

    const int n = in_sizes[0] / F;        // 50000
    const int e = in_sizes[2];            // 800000
    const int* src = ei;
    const int* dst = ei + e;

    const int TB = 256;
    auto cdiv = [](long long a, long long b) { return (int)((a + b - 1) / b); };
    int nb = cdiv(n, 256);
    int lnBlocks = cdiv((long long)n * 32, TB);
    int degBlocks = cdiv(e, TB);

    k_setup <<<cdiv(n, TB), TB>>>(cw, gw, as, ad, n);
    k_lndeg <<<lnBlocks + degBlocks, TB>>>(x, lng, lnb, src, dst, ea, n, e, lnBlocks);
    k_scan1 <<<nb, 256>>>(n);
    k_scan2 <<<1, 256>>>(nb);
    k_scan3 <<<cdiv(n, TB), TB>>>(n, e);
    k_fill  <<<cdiv(e, TB), TB>>>(src, dst, ea, e);
    k_prop  <<<cdiv((long long)n * 32, TB), TB>>>(n, 0);
    k_prop  <<<cdiv((long long)n * 32, TB), TB>>>(n, 1);
    k_mma1  <<<cdiv(n, 128), 256>>>(cb, n);
    k_gat   <<<cdiv((long long)n * 32, TB), TB>>>(n);
    k_mma2  <<<cdiv(n, 128), 256>>>(gb, out, n);
}